// round 1
// baseline (speedup 1.0000x reference)
#include <cuda_runtime.h>

#define BATCH 4
#define SEQL  4096
#define DIN   128
#define NST   16
#define TCH   32
#define NCH   128   /* SEQL / TCH */

// ---------------- scratch (device globals; no allocation) ----------------
__device__ float g_xr  [BATCH*SEQL*256];   // in_proj output (u | res)
__device__ float g_u   [BATCH*SEQL*DIN];   // silu(conv(u))
__device__ float g_xdbl[BATCH*SEQL*36];    // x_proj output (dt4 | B16 | C16)
__device__ float g_hp  [BATCH*NCH*DIN*32]; // per-chunk [h_end(16) | P(16)] -> becomes H_init
__device__ float g_yg  [BATCH*SEQL*DIN];   // gated scan output
__device__ float g_xmid[BATCH*SEQL*64];    // between mambas
__device__ float g_w1t [64*256];           // in_proj weight, transposed [k][n]
__device__ float g_wxt [128*64];           // x_proj weight, transposed + zero-padded to 64
__device__ float g_wot [128*64];           // out_proj weight, transposed
__device__ float g_Ab  [DIN*NST];          // A = -exp(Alog)

__device__ __forceinline__ float softplusf(float x) {
    return x > 15.f ? x : log1pf(__expf(x));
}
__device__ __forceinline__ float siluf(float x) {
    return x / (1.f + __expf(-x));
}

// ---------------- prep: weight transposes + A ----------------
__global__ void prep_k(const float* __restrict__ in_w, const float* __restrict__ xproj,
                       const float* __restrict__ out_w, const float* __restrict__ Alog,
                       float* __restrict__ w1t, float* __restrict__ wxt,
                       float* __restrict__ wot, float* __restrict__ Ab) {
    int idx = blockIdx.x * 256 + threadIdx.x;
    if (idx < 16384) { int k = idx >> 8, n = idx & 255; w1t[idx] = in_w[n*64 + k]; return; }
    idx -= 16384;
    if (idx < 8192)  { int k = idx >> 6, n = idx & 63; wxt[idx] = (n < 36) ? xproj[n*128 + k] : 0.f; return; }
    idx -= 8192;
    if (idx < 8192)  { int k = idx >> 6, n = idx & 63; wot[idx] = out_w[n*128 + k]; return; }
    idx -= 8192;
    if (idx < 2048)  Ab[idx] = -expf(Alog[idx]);
}

// ---------------- generic 64x64x64-tiled GEMM: out[b,l,n] = sum_k X[b,l,k] * W[n,k] ----------------
// Wt is pre-transposed [K][Nld]. epi: 0 = plain write (Nout), 1 = write cols<36 to (b,L,36),
// 2 = LayerNorm over the 64 cols (requires N-tile covers full width), optional transposed output.
__global__ __launch_bounds__(256) void gemm64_k(
    const float* __restrict__ X, const float* __restrict__ Wt, float* __restrict__ Out,
    int K, int Nld, int Nout,
    long xsb, long xsl, long xsk,
    int epi, const float* __restrict__ lng, const float* __restrict__ lnb, int trans_out)
{
    __shared__ float xs[64][68];  // [k][l], padded
    __shared__ float ws[64][64];  // [k][n]
    int tid = threadIdx.x;
    int l0 = blockIdx.x << 6;
    int n0 = blockIdx.y << 6;
    int b  = blockIdx.z;
    const float* Xb = X + (long)b * xsb;
    int lj = tid & 15, ng = tid >> 4;

    float acc[4][4];
#pragma unroll
    for (int r = 0; r < 4; r++)
#pragma unroll
        for (int c = 0; c < 4; c++) acc[r][c] = 0.f;

    for (int k0 = 0; k0 < K; k0 += 64) {
#pragma unroll
        for (int i = 0; i < 16; i++) {
            int e = tid + (i << 8);
            ws[e >> 6][e & 63] = Wt[(long)(k0 + (e >> 6)) * Nld + n0 + (e & 63)];
        }
        if (xsk == 1) {
#pragma unroll
            for (int i = 0; i < 16; i++) {
                int e = tid + (i << 8);
                xs[e & 63][e >> 6] = Xb[(long)(l0 + (e >> 6)) * xsl + k0 + (e & 63)];
            }
        } else {
#pragma unroll
            for (int i = 0; i < 16; i++) {
                int e = tid + (i << 8);
                xs[e >> 6][e & 63] = Xb[(long)(k0 + (e >> 6)) * xsk + l0 + (e & 63)];
            }
        }
        __syncthreads();
#pragma unroll 16
        for (int kk = 0; kk < 64; kk++) {
            float4 av = *(const float4*)&xs[kk][lj << 2];
            float4 bv = *(const float4*)&ws[kk][ng << 2];
            float a4[4] = {av.x, av.y, av.z, av.w};
            float b4[4] = {bv.x, bv.y, bv.z, bv.w};
#pragma unroll
            for (int r = 0; r < 4; r++)
#pragma unroll
                for (int c = 0; c < 4; c++)
                    acc[r][c] = fmaf(a4[r], b4[c], acc[r][c]);
        }
        __syncthreads();
    }

    if (epi == 0) {
#pragma unroll
        for (int r = 0; r < 4; r++) {
            long row = (long)b * SEQL + l0 + (lj << 2) + r;
            float4 v = make_float4(acc[r][0], acc[r][1], acc[r][2], acc[r][3]);
            *(float4*)&Out[row * Nout + n0 + (ng << 2)] = v;
        }
    } else if (epi == 1) {
#pragma unroll
        for (int r = 0; r < 4; r++) {
            long row = (long)b * SEQL + l0 + (lj << 2) + r;
#pragma unroll
            for (int c = 0; c < 4; c++) {
                int n = n0 + (ng << 2) + c;
                if (n < 36) Out[row * 36 + n] = acc[r][c];
            }
        }
    } else {
        // LayerNorm epilogue over all 64 cols of each of 64 rows (n0 == 0, grid.y == 1)
#pragma unroll
        for (int r = 0; r < 4; r++)
#pragma unroll
            for (int c = 0; c < 4; c++)
                xs[(lj << 2) + r][(ng << 2) + c] = acc[r][c];
        __syncthreads();
        int row = tid >> 2, q = tid & 3;
        float v[16], s = 0.f, s2 = 0.f;
#pragma unroll
        for (int j = 0; j < 16; j++) {
            float x = xs[row][q * 16 + j];
            v[j] = x; s += x; s2 += x * x;
        }
        s  += __shfl_xor_sync(0xffffffffu, s, 1);
        s2 += __shfl_xor_sync(0xffffffffu, s2, 1);
        s  += __shfl_xor_sync(0xffffffffu, s, 2);
        s2 += __shfl_xor_sync(0xffffffffu, s2, 2);
        float mean = s * 0.015625f;
        float var  = s2 * 0.015625f - mean * mean;
        float rstd = rsqrtf(var + 1e-5f);
        if (!trans_out) {
#pragma unroll
            for (int j = 0; j < 16; j++) {
                int n = q * 16 + j;
                Out[((long)b * SEQL + l0 + row) * 64 + n] =
                    (v[j] - mean) * rstd * __ldg(&lng[n]) + __ldg(&lnb[n]);
            }
        } else {
#pragma unroll
            for (int j = 0; j < 16; j++) {
                int n = q * 16 + j;
                Out[((long)b * 64 + n) * SEQL + l0 + row] =
                    (v[j] - mean) * rstd * __ldg(&lng[n]) + __ldg(&lnb[n]);
            }
        }
    }
}

// ---------------- causal depthwise conv (k=4) + silu ----------------
__global__ void conv_silu_k(const float* __restrict__ xr, const float* __restrict__ cw,
                            const float* __restrict__ cb, float* __restrict__ u) {
    int idx = blockIdx.x * 256 + threadIdx.x;     // (b*L + l)*128 + d
    int d = idx & 127;
    int l = (idx >> 7) & (SEQL - 1);
    const float4 w = *(const float4*)&cw[d * 4];
    const float* p = xr + (long)(idx >> 7) * 256 + d;
    float s = __ldg(&cb[d]) + w.w * p[0];
    if (l >= 1) s += w.z * p[-256];
    if (l >= 2) s += w.y * p[-512];
    if (l >= 3) s += w.x * p[-768];
    u[idx] = siluf(s);
}

// ---------------- scan pass 1: per-chunk local scan from h=0; emit h_end and P=prod(a) ----------------
__global__ __launch_bounds__(128) void scan1_k(const float* __restrict__ u,
                                               const float* __restrict__ xdbl,
                                               const float* __restrict__ Ap,
                                               const float* __restrict__ dtw,
                                               const float* __restrict__ dtb,
                                               float* __restrict__ hp) {
    __shared__ float xd[TCH][36];
    __shared__ float us[TCH][128];
    int d = threadIdx.x;
    int c = blockIdx.x, b = blockIdx.y;
    long l0 = (long)b * SEQL + c * TCH;
    for (int e = d; e < TCH * 36; e += 128) xd[e / 36][e % 36] = xdbl[l0 * 36 + e];
    for (int e = d; e < TCH * 128; e += 128) us[e >> 7][e & 127] = u[l0 * 128 + e];
    float4 w = *(const float4*)&dtw[d * 4];
    float bias = __ldg(&dtb[d]);
    float Ar[NST];
#pragma unroll
    for (int n = 0; n < NST; n++) Ar[n] = Ap[d * NST + n];
    float h[NST], P[NST];
#pragma unroll
    for (int n = 0; n < NST; n++) { h[n] = 0.f; P[n] = 1.f; }
    __syncthreads();
    for (int t = 0; t < TCH; t++) {
        float dt = fmaf(xd[t][0], w.x, fmaf(xd[t][1], w.y, fmaf(xd[t][2], w.z, fmaf(xd[t][3], w.w, bias))));
        dt = softplusf(dt);
        float du = dt * us[t][d];
#pragma unroll
        for (int n = 0; n < NST; n++) {
            float a = __expf(dt * Ar[n]);
            h[n] = fmaf(a, h[n], du * xd[t][4 + n]);
            P[n] *= a;
        }
    }
    float* o = hp + (((long)b * NCH + c) * DIN + d) * 32;
#pragma unroll
    for (int n = 0; n < NST; n++) { o[n] = h[n]; o[16 + n] = P[n]; }
}

// ---------------- scan pass 2: sequential chunk combine; rewrite slot with H_init(chunk) ----------------
__global__ void scan2_k(float* __restrict__ hp) {
    int idx = blockIdx.x * 256 + threadIdx.x;   // B*128*16 = 8192 threads
    int dn = idx & 2047;
    int b = idx >> 11;
    int off = ((dn >> 4) << 5) + (dn & 15);     // d*32 + n
    long base = (long)b * NCH * (DIN * 32) + off;
    float H = 0.f;
    for (int c = 0; c < NCH; c++) {
        float he = hp[base];
        float p  = hp[base + 16];
        hp[base] = H;                // state BEFORE this chunk
        H = fmaf(p, H, he);
        base += DIN * 32;
    }
}

// ---------------- scan pass 3: replay from H_init; y = C.h + u*D; gate by silu(res) ----------------
__global__ __launch_bounds__(128) void scan3_k(const float* __restrict__ u,
                                               const float* __restrict__ xdbl,
                                               const float* __restrict__ xr,
                                               const float* __restrict__ Ap,
                                               const float* __restrict__ dtw,
                                               const float* __restrict__ dtb,
                                               const float* __restrict__ Dp,
                                               const float* __restrict__ hp,
                                               float* __restrict__ yg) {
    __shared__ float xd[TCH][36];
    __shared__ float us[TCH][128];
    __shared__ float rs[TCH][128];
    int d = threadIdx.x;
    int c = blockIdx.x, b = blockIdx.y;
    long l0 = (long)b * SEQL + c * TCH;
    for (int e = d; e < TCH * 36; e += 128) xd[e / 36][e % 36] = xdbl[l0 * 36 + e];
    for (int e = d; e < TCH * 128; e += 128) {
        us[e >> 7][e & 127] = u[l0 * 128 + e];
        rs[e >> 7][e & 127] = xr[(l0 + (e >> 7)) * 256 + 128 + (e & 127)];
    }
    float4 w = *(const float4*)&dtw[d * 4];
    float bias = __ldg(&dtb[d]);
    float Dd = __ldg(&Dp[d]);
    float Ar[NST];
#pragma unroll
    for (int n = 0; n < NST; n++) Ar[n] = Ap[d * NST + n];
    float h[NST];
    const float* hi = hp + (((long)b * NCH + c) * DIN + d) * 32;
#pragma unroll
    for (int n = 0; n < NST; n++) h[n] = hi[n];
    __syncthreads();
    for (int t = 0; t < TCH; t++) {
        float dt = fmaf(xd[t][0], w.x, fmaf(xd[t][1], w.y, fmaf(xd[t][2], w.z, fmaf(xd[t][3], w.w, bias))));
        dt = softplusf(dt);
        float du = dt * us[t][d];
        float y = 0.f;
#pragma unroll
        for (int n = 0; n < NST; n++) {
            float a = __expf(dt * Ar[n]);
            h[n] = fmaf(a, h[n], du * xd[t][4 + n]);
            y = fmaf(h[n], xd[t][20 + n], y);
        }
        float val = fmaf(us[t][d], Dd, y);
        yg[(l0 + t) * 128 + d] = val * siluf(rs[t][d]);
    }
}

// ---------------- host ----------------
extern "C" void kernel_launch(void* const* d_in, const int* in_sizes, int n_in,
                              void* d_out, int out_size) {
    const float* x1 = (const float*)d_in[0];
    float* out = (float*)d_out;

    float *xr, *u, *xd, *hp, *yg, *xmid, *w1t, *wxt, *wot, *Ab;
    cudaGetSymbolAddress((void**)&xr,   g_xr);
    cudaGetSymbolAddress((void**)&u,    g_u);
    cudaGetSymbolAddress((void**)&xd,   g_xdbl);
    cudaGetSymbolAddress((void**)&hp,   g_hp);
    cudaGetSymbolAddress((void**)&yg,   g_yg);
    cudaGetSymbolAddress((void**)&xmid, g_xmid);
    cudaGetSymbolAddress((void**)&w1t,  g_w1t);
    cudaGetSymbolAddress((void**)&wxt,  g_wxt);
    cudaGetSymbolAddress((void**)&wot,  g_wot);
    cudaGetSymbolAddress((void**)&Ab,   g_Ab);

    for (int m = 0; m < 2; m++) {
        const float* in_w  = (const float*)d_in[1 + 9 * m + 0];
        const float* cw    = (const float*)d_in[1 + 9 * m + 1];
        const float* cb    = (const float*)d_in[1 + 9 * m + 2];
        const float* xproj = (const float*)d_in[1 + 9 * m + 3];
        const float* dtw   = (const float*)d_in[1 + 9 * m + 4];
        const float* dtb   = (const float*)d_in[1 + 9 * m + 5];
        const float* Alog  = (const float*)d_in[1 + 9 * m + 6];
        const float* Dp    = (const float*)d_in[1 + 9 * m + 7];
        const float* outw  = (const float*)d_in[1 + 9 * m + 8];
        const float* lng   = (const float*)d_in[19 + 2 * m];
        const float* lnb   = (const float*)d_in[20 + 2 * m];

        const float* Xin; long xsb, xsl, xsk; float* gout; int trans;
        if (m == 0) { Xin = x1;   xsb = 64L * SEQL;      xsl = 1;  xsk = SEQL; gout = xmid; trans = 0; }
        else        { Xin = xmid; xsb = (long)SEQL * 64; xsl = 64; xsk = 1;    gout = out;  trans = 1; }

        prep_k<<<136, 256>>>(in_w, xproj, outw, Alog, w1t, wxt, wot, Ab);

        // in_proj: (B*L,64) @ (64,256)^T
        gemm64_k<<<dim3(SEQL / 64, 4, BATCH), 256>>>(Xin, w1t, xr, 64, 256, 256,
                                                     xsb, xsl, xsk, 0, nullptr, nullptr, 0);
        // conv + silu
        conv_silu_k<<<(BATCH * SEQL * DIN) / 256, 256>>>(xr, cw, cb, u);
        // x_proj: (B*L,128) @ (128,36)^T (padded to 64)
        gemm64_k<<<dim3(SEQL / 64, 1, BATCH), 256>>>(u, wxt, xd, 128, 64, 36,
                                                     (long)SEQL * DIN, DIN, 1, 1, nullptr, nullptr, 0);
        // chunked selective scan
        scan1_k<<<dim3(NCH, BATCH), DIN>>>(u, xd, Ab, dtw, dtb, hp);
        scan2_k<<<32, 256>>>(hp);
        scan3_k<<<dim3(NCH, BATCH), DIN>>>(u, xd, xr, Ab, dtw, dtb, Dp, hp, yg);
        // out_proj + LayerNorm (+ transpose on final)
        gemm64_k<<<dim3(SEQL / 64, 1, BATCH), 256>>>(yg, wot, gout, 128, 64, 64,
                                                     (long)SEQL * DIN, DIN, 1, 2, lng, lnb, trans);
    }
}

// round 2
// speedup vs baseline: 1.0347x; 1.0347x over previous
#include <cuda_runtime.h>

#define BATCH 4
#define SEQL  4096
#define DIN   128
#define NST   16
#define TCH   32
#define NCH   128   /* SEQL / TCH */

typedef unsigned long long u64;

#define FMA2(d, a, b, c) asm("fma.rn.f32x2 %0, %1, %2, %3;" : "=l"(d) : "l"(a), "l"(b), "l"(c))
#define UNPK2(x, y, in)  asm("mov.b64 {%0, %1}, %2;" : "=f"(x), "=f"(y) : "l"(in))

// ---------------- scratch (device globals; no allocation) ----------------
__device__ float g_xr  [BATCH*SEQL*256];   // in_proj output (u | res)
__device__ float g_u   [BATCH*SEQL*DIN];   // silu(conv(u))
__device__ float g_xdbl[BATCH*SEQL*36];    // x_proj output (dt4 | B16 | C16)
__device__ float g_hp  [BATCH*NCH*DIN*32]; // per-chunk [h_end(16) | P(16)] -> becomes H_init
__device__ float g_yg  [BATCH*SEQL*DIN];   // gated scan output
__device__ float g_xmid[BATCH*SEQL*64];    // between mambas
__device__ float g_w1t [2][64*256];        // in_proj weight, transposed [k][n]
__device__ float g_wxt [2][128*64];        // x_proj weight, transposed + zero-padded to 64
__device__ float g_wot [2][128*64];        // out_proj weight, transposed
__device__ float g_Ab  [2][DIN*NST];       // A = -exp(Alog)
__device__ int   g_Afl [2];                // 1 if A[d][n] == (n+1)*A[d][0]

__device__ __forceinline__ float softplusf(float x) {
    return x > 15.f ? x : __logf(1.f + __expf(x));
}
__device__ __forceinline__ float siluf(float x) {
    return x / (1.f + __expf(-x));
}

// ---------------- prep: weight transposes + A ----------------
__global__ void prep_k(const float* __restrict__ in_w, const float* __restrict__ xproj,
                       const float* __restrict__ out_w, const float* __restrict__ Alog,
                       float* __restrict__ w1t, float* __restrict__ wxt,
                       float* __restrict__ wot, float* __restrict__ Ab) {
    int idx = blockIdx.x * 256 + threadIdx.x;
    if (idx < 16384) { int k = idx >> 8, n = idx & 255; w1t[idx] = in_w[n*64 + k]; return; }
    idx -= 16384;
    if (idx < 8192)  { int k = idx >> 6, n = idx & 63; wxt[idx] = (n < 36) ? xproj[n*128 + k] : 0.f; return; }
    idx -= 8192;
    if (idx < 8192)  { int k = idx >> 6, n = idx & 63; wot[idx] = out_w[n*128 + k]; return; }
    idx -= 8192;
    if (idx < 2048)  Ab[idx] = -expf(Alog[idx]);
}

// ---------------- check structured A: A[d][n] = (n+1)*A[d][0] ----------------
__global__ void chkA_k(const float* __restrict__ A0, const float* __restrict__ A1,
                       int* __restrict__ fl) {
    const float* A = blockIdx.x ? A1 : A0;
    __shared__ int ok;
    if (threadIdx.x == 0) ok = 1;
    __syncthreads();
    int bad = 0;
    for (int e = threadIdx.x; e < DIN*NST; e += 256) {
        int d = e >> 4, n = e & 15;
        float expv = (float)(n + 1) * A[d*16];
        if (fabsf(A[e] - expv) > 1e-5f * fabsf(expv) + 1e-20f) bad = 1;
    }
    if (bad) atomicAnd(&ok, 0);
    __syncthreads();
    if (threadIdx.x == 0) fl[blockIdx.x] = ok;
}

// ---------------- 64x64x64-tiled GEMM with FFMA2 mainloop ----------------
// Wt pre-transposed [K][Nld]. epi: 0 plain (Nout), 1 cols<36 to (b,L,36),
// 2 LayerNorm over 64 cols (grid.y==1), optional transposed (coalesced) output.
__global__ __launch_bounds__(256) void gemm64_k(
    const float* __restrict__ X, const float* __restrict__ Wt, float* __restrict__ Out,
    int K, int Nld, int Nout,
    long xsb, long xsl, long xsk,
    int epi, const float* __restrict__ lng, const float* __restrict__ lnb, int trans_out)
{
    __shared__ float xs[64][68];    // [k][l], 17 float4 per row (16B-aligned rows)
    __shared__ float ws2[64][128];  // [k][2n] duplicated: ws2[k][2n]=ws2[k][2n+1]=W[k][n]
    int tid = threadIdx.x;
    int l0 = blockIdx.x << 6;
    int n0 = blockIdx.y << 6;
    int b  = blockIdx.z;
    const float* Xb = X + (long)b * xsb;
    int lj = tid & 15, ng = tid >> 4;

    u64 acc0[4], acc1[4];   // row-pairs (l+0,l+1) and (l+2,l+3), 4 cols each
#pragma unroll
    for (int c = 0; c < 4; c++) { acc0[c] = 0ULL; acc1[c] = 0ULL; }

    for (int k0 = 0; k0 < K; k0 += 64) {
#pragma unroll
        for (int i = 0; i < 4; i++) {
            int s = tid + (i << 8);
            int k = s >> 4, nq = s & 15;
            float4 w = *(const float4*)&Wt[(long)(k0 + k) * Nld + n0 + (nq << 2)];
            *(float4*)&ws2[k][nq << 3]       = make_float4(w.x, w.x, w.y, w.y);
            *(float4*)&ws2[k][(nq << 3) + 4] = make_float4(w.z, w.z, w.w, w.w);
        }
        if (xsk == 1) {
            int l = tid >> 2, kq = tid & 3;
#pragma unroll
            for (int i = 0; i < 4; i++) {
                int kk = (kq << 4) + (i << 2);
                float4 v = *(const float4*)&Xb[(long)(l0 + l) * xsl + k0 + kk];
                xs[kk][l] = v.x; xs[kk+1][l] = v.y; xs[kk+2][l] = v.z; xs[kk+3][l] = v.w;
            }
        } else {
#pragma unroll
            for (int i = 0; i < 4; i++) {
                int s = tid + (i << 8);
                int k = s >> 4, lq = s & 15;
                *(float4*)&xs[k][lq << 2] =
                    *(const float4*)&Xb[(long)(k0 + k) * xsk + l0 + (lq << 2)];
            }
        }
        __syncthreads();
#pragma unroll 16
        for (int kk = 0; kk < 64; kk++) {
            ulonglong2 aq = *(const ulonglong2*)&xs[kk][lj << 2];      // (l0,l1),(l2,l3)
            ulonglong2 bq0 = *(const ulonglong2*)&ws2[kk][ng << 3];    // (b0,b0),(b1,b1)
            ulonglong2 bq1 = *(const ulonglong2*)&ws2[kk][(ng << 3) + 4];
            FMA2(acc0[0], aq.x, bq0.x, acc0[0]); FMA2(acc1[0], aq.y, bq0.x, acc1[0]);
            FMA2(acc0[1], aq.x, bq0.y, acc0[1]); FMA2(acc1[1], aq.y, bq0.y, acc1[1]);
            FMA2(acc0[2], aq.x, bq1.x, acc0[2]); FMA2(acc1[2], aq.y, bq1.x, acc1[2]);
            FMA2(acc0[3], aq.x, bq1.y, acc0[3]); FMA2(acc1[3], aq.y, bq1.y, acc1[3]);
        }
        __syncthreads();
    }

    float acc[4][4];
#pragma unroll
    for (int c = 0; c < 4; c++) {
        UNPK2(acc[0][c], acc[1][c], acc0[c]);
        UNPK2(acc[2][c], acc[3][c], acc1[c]);
    }

    if (epi == 0) {
#pragma unroll
        for (int r = 0; r < 4; r++) {
            long row = (long)b * SEQL + l0 + (lj << 2) + r;
            float4 v = make_float4(acc[r][0], acc[r][1], acc[r][2], acc[r][3]);
            *(float4*)&Out[row * Nout + n0 + (ng << 2)] = v;
        }
    } else if (epi == 1) {
#pragma unroll
        for (int r = 0; r < 4; r++) {
            long row = (long)b * SEQL + l0 + (lj << 2) + r;
#pragma unroll
            for (int c = 0; c < 4; c++) {
                int n = n0 + (ng << 2) + c;
                if (n < 36) Out[row * 36 + n] = acc[r][c];
            }
        }
    } else {
        // LayerNorm over all 64 cols of 64 rows (n0 == 0, grid.y == 1)
#pragma unroll
        for (int r = 0; r < 4; r++)
#pragma unroll
            for (int c = 0; c < 4; c++)
                xs[(lj << 2) + r][(ng << 2) + c] = acc[r][c];
        __syncthreads();
        int row = tid >> 2, q = tid & 3;
        float v[16], s = 0.f, s2 = 0.f;
#pragma unroll
        for (int j = 0; j < 16; j++) {
            float x = xs[row][q * 16 + j];
            v[j] = x; s += x; s2 += x * x;
        }
        s  += __shfl_xor_sync(0xffffffffu, s, 1);
        s2 += __shfl_xor_sync(0xffffffffu, s2, 1);
        s  += __shfl_xor_sync(0xffffffffu, s, 2);
        s2 += __shfl_xor_sync(0xffffffffu, s2, 2);
        float mean = s * 0.015625f;
        float var  = s2 * 0.015625f - mean * mean;
        float rstd = rsqrtf(var + 1e-5f);
        if (!trans_out) {
#pragma unroll
            for (int j = 0; j < 16; j++) {
                int n = q * 16 + j;
                Out[((long)b * SEQL + l0 + row) * 64 + n] =
                    (v[j] - mean) * rstd * __ldg(&lng[n]) + __ldg(&lnb[n]);
            }
        } else {
            // stage transposed tile in smem, then coalesced float4 stores along L
            __syncthreads();
#pragma unroll
            for (int j = 0; j < 16; j++) {
                int n = q * 16 + j;
                xs[n][row] = (v[j] - mean) * rstd * __ldg(&lng[n]) + __ldg(&lnb[n]);
            }
            __syncthreads();
            int n = tid >> 2, lq = tid & 3;
#pragma unroll
            for (int i = 0; i < 4; i++) {
                int lc = (lq << 4) + (i << 2);
                float4 v4 = make_float4(xs[n][lc], xs[n][lc+1], xs[n][lc+2], xs[n][lc+3]);
                *(float4*)&Out[((long)b * 64 + n) * SEQL + l0 + lc] = v4;
            }
        }
    }
}

// ---------------- causal depthwise conv (k=4) + silu ----------------
__global__ void conv_silu_k(const float* __restrict__ xr, const float* __restrict__ cw,
                            const float* __restrict__ cb, float* __restrict__ u) {
    int idx = blockIdx.x * 256 + threadIdx.x;     // (b*L + l)*128 + d
    int d = idx & 127;
    int l = (idx >> 7) & (SEQL - 1);
    const float4 w = *(const float4*)&cw[d * 4];
    const float* p = xr + (long)(idx >> 7) * 256 + d;
    float s = __ldg(&cb[d]) + w.w * p[0];
    if (l >= 1) s += w.z * p[-256];
    if (l >= 2) s += w.y * p[-512];
    if (l >= 3) s += w.x * p[-768];
    u[idx] = siluf(s);
}

// ---------------- scan pass 1: per-chunk local scan from h=0; emit h_end, P=exp(A*sum_dt) ----------------
__global__ __launch_bounds__(128) void scan1_k(const float* __restrict__ u,
                                               const float* __restrict__ xdbl,
                                               const float* __restrict__ Ap,
                                               const float* __restrict__ dtw,
                                               const float* __restrict__ dtb,
                                               float* __restrict__ hp,
                                               const int* __restrict__ flagp) {
    __shared__ float xd[TCH][36];
    __shared__ float us[TCH][128];
    int d = threadIdx.x;
    int c = blockIdx.x, b = blockIdx.y;
    long l0 = (long)b * SEQL + c * TCH;
    for (int e = d; e < TCH * 36; e += 128) xd[e / 36][e % 36] = xdbl[l0 * 36 + e];
    for (int e = d; e < TCH * 128; e += 128) us[e >> 7][e & 127] = u[l0 * 128 + e];
    float4 w = *(const float4*)&dtw[d * 4];
    float bias = __ldg(&dtb[d]);
    int structured = *flagp;
    float Ar[NST];
#pragma unroll
    for (int n = 0; n < NST; n++) Ar[n] = Ap[d * NST + n];
    float h[NST], S = 0.f;
#pragma unroll
    for (int n = 0; n < NST; n++) h[n] = 0.f;
    __syncthreads();
    if (structured) {
        float A0 = Ar[0];
        for (int t = 0; t < TCH; t++) {
            float dt = fmaf(xd[t][0], w.x, fmaf(xd[t][1], w.y, fmaf(xd[t][2], w.z, fmaf(xd[t][3], w.w, bias))));
            dt = softplusf(dt);
            S += dt;
            float du = dt * us[t][d];
            float r = __expf(dt * A0);
            float a = r;
#pragma unroll
            for (int n = 0; n < NST; n++) {
                h[n] = fmaf(a, h[n], du * xd[t][4 + n]);
                if (n < NST - 1) a *= r;
            }
        }
    } else {
        for (int t = 0; t < TCH; t++) {
            float dt = fmaf(xd[t][0], w.x, fmaf(xd[t][1], w.y, fmaf(xd[t][2], w.z, fmaf(xd[t][3], w.w, bias))));
            dt = softplusf(dt);
            S += dt;
            float du = dt * us[t][d];
#pragma unroll
            for (int n = 0; n < NST; n++) {
                float a = __expf(dt * Ar[n]);
                h[n] = fmaf(a, h[n], du * xd[t][4 + n]);
            }
        }
    }
    float* o = hp + (((long)b * NCH + c) * DIN + d) * 32;
#pragma unroll
    for (int n = 0; n < NST; n++) { o[n] = h[n]; o[16 + n] = __expf(S * Ar[n]); }
}

// ---------------- scan pass 2: sequential chunk combine; rewrite slot with H_init(chunk) ----------------
__global__ void scan2_k(float* __restrict__ hp) {
    int idx = blockIdx.x * 256 + threadIdx.x;   // B*128*16 = 8192 threads
    int dn = idx & 2047;
    int b = idx >> 11;
    int off = ((dn >> 4) << 5) + (dn & 15);     // d*32 + n
    long base = (long)b * NCH * (DIN * 32) + off;
    float H = 0.f;
    for (int c = 0; c < NCH; c++) {
        float he = hp[base];
        float p  = hp[base + 16];
        hp[base] = H;                // state BEFORE this chunk
        H = fmaf(p, H, he);
        base += DIN * 32;
    }
}

// ---------------- scan pass 3: replay from H_init; y = C.h + u*D; gate by silu(res) ----------------
__global__ __launch_bounds__(128) void scan3_k(const float* __restrict__ u,
                                               const float* __restrict__ xdbl,
                                               const float* __restrict__ xr,
                                               const float* __restrict__ Ap,
                                               const float* __restrict__ dtw,
                                               const float* __restrict__ dtb,
                                               const float* __restrict__ Dp,
                                               const float* __restrict__ hp,
                                               float* __restrict__ yg,
                                               const int* __restrict__ flagp) {
    __shared__ float xd[TCH][36];
    __shared__ float us[TCH][128];
    __shared__ float rs[TCH][128];
    int d = threadIdx.x;
    int c = blockIdx.x, b = blockIdx.y;
    long l0 = (long)b * SEQL + c * TCH;
    for (int e = d; e < TCH * 36; e += 128) xd[e / 36][e % 36] = xdbl[l0 * 36 + e];
    for (int e = d; e < TCH * 128; e += 128) {
        us[e >> 7][e & 127] = u[l0 * 128 + e];
        rs[e >> 7][e & 127] = xr[(l0 + (e >> 7)) * 256 + 128 + (e & 127)];
    }
    float4 w = *(const float4*)&dtw[d * 4];
    float bias = __ldg(&dtb[d]);
    float Dd = __ldg(&Dp[d]);
    int structured = *flagp;
    float Ar[NST];
#pragma unroll
    for (int n = 0; n < NST; n++) Ar[n] = Ap[d * NST + n];
    float h[NST];
    const float* hi = hp + (((long)b * NCH + c) * DIN + d) * 32;
#pragma unroll
    for (int n = 0; n < NST; n++) h[n] = hi[n];
    __syncthreads();
    if (structured) {
        float A0 = Ar[0];
        for (int t = 0; t < TCH; t++) {
            float dt = fmaf(xd[t][0], w.x, fmaf(xd[t][1], w.y, fmaf(xd[t][2], w.z, fmaf(xd[t][3], w.w, bias))));
            dt = softplusf(dt);
            float du = dt * us[t][d];
            float r = __expf(dt * A0);
            float a = r;
            float y = 0.f;
#pragma unroll
            for (int n = 0; n < NST; n++) {
                h[n] = fmaf(a, h[n], du * xd[t][4 + n]);
                y = fmaf(h[n], xd[t][20 + n], y);
                if (n < NST - 1) a *= r;
            }
            float val = fmaf(us[t][d], Dd, y);
            yg[(l0 + t) * 128 + d] = val * siluf(rs[t][d]);
        }
    } else {
        for (int t = 0; t < TCH; t++) {
            float dt = fmaf(xd[t][0], w.x, fmaf(xd[t][1], w.y, fmaf(xd[t][2], w.z, fmaf(xd[t][3], w.w, bias))));
            dt = softplusf(dt);
            float du = dt * us[t][d];
            float y = 0.f;
#pragma unroll
            for (int n = 0; n < NST; n++) {
                float a = __expf(dt * Ar[n]);
                h[n] = fmaf(a, h[n], du * xd[t][4 + n]);
                y = fmaf(h[n], xd[t][20 + n], y);
            }
            float val = fmaf(us[t][d], Dd, y);
            yg[(l0 + t) * 128 + d] = val * siluf(rs[t][d]);
        }
    }
}

// ---------------- host ----------------
extern "C" void kernel_launch(void* const* d_in, const int* in_sizes, int n_in,
                              void* d_out, int out_size) {
    const float* x1 = (const float*)d_in[0];
    float* out = (float*)d_out;

    float *xr, *u, *xd, *hp, *yg, *xmid, *w1t, *wxt, *wot, *Ab;
    int* Afl;
    cudaGetSymbolAddress((void**)&xr,   g_xr);
    cudaGetSymbolAddress((void**)&u,    g_u);
    cudaGetSymbolAddress((void**)&xd,   g_xdbl);
    cudaGetSymbolAddress((void**)&hp,   g_hp);
    cudaGetSymbolAddress((void**)&yg,   g_yg);
    cudaGetSymbolAddress((void**)&xmid, g_xmid);
    cudaGetSymbolAddress((void**)&w1t,  g_w1t);
    cudaGetSymbolAddress((void**)&wxt,  g_wxt);
    cudaGetSymbolAddress((void**)&wot,  g_wot);
    cudaGetSymbolAddress((void**)&Ab,   g_Ab);
    cudaGetSymbolAddress((void**)&Afl,  g_Afl);

    // prep both mambas up front
    for (int m = 0; m < 2; m++) {
        prep_k<<<136, 256>>>((const float*)d_in[1 + 9*m + 0], (const float*)d_in[1 + 9*m + 3],
                             (const float*)d_in[1 + 9*m + 8], (const float*)d_in[1 + 9*m + 6],
                             w1t + m*16384, wxt + m*8192, wot + m*8192, Ab + m*2048);
    }
    chkA_k<<<2, 256>>>(Ab, Ab + 2048, Afl);

    for (int m = 0; m < 2; m++) {
        const float* cw    = (const float*)d_in[1 + 9 * m + 1];
        const float* cb    = (const float*)d_in[1 + 9 * m + 2];
        const float* dtw   = (const float*)d_in[1 + 9 * m + 4];
        const float* dtb   = (const float*)d_in[1 + 9 * m + 5];
        const float* Dp    = (const float*)d_in[1 + 9 * m + 7];
        const float* lng   = (const float*)d_in[19 + 2 * m];
        const float* lnb   = (const float*)d_in[20 + 2 * m];
        const float* Abm   = Ab + m * 2048;
        const int*   flm   = Afl + m;

        const float* Xin; long xsb, xsl, xsk; float* gout; int trans;
        if (m == 0) { Xin = x1;   xsb = 64L * SEQL;      xsl = 1;  xsk = SEQL; gout = xmid; trans = 0; }
        else        { Xin = xmid; xsb = (long)SEQL * 64; xsl = 64; xsk = 1;    gout = out;  trans = 1; }

        // in_proj: (B*L,64) @ (64,256)^T
        gemm64_k<<<dim3(SEQL / 64, 4, BATCH), 256>>>(Xin, w1t + m*16384, xr, 64, 256, 256,
                                                     xsb, xsl, xsk, 0, nullptr, nullptr, 0);
        // conv + silu
        conv_silu_k<<<(BATCH * SEQL * DIN) / 256, 256>>>(xr, cw, cb, u);
        // x_proj: (B*L,128) @ (128,36)^T (padded to 64)
        gemm64_k<<<dim3(SEQL / 64, 1, BATCH), 256>>>(u, wxt + m*8192, xd, 128, 64, 36,
                                                     (long)SEQL * DIN, DIN, 1, 1, nullptr, nullptr, 0);
        // chunked selective scan
        scan1_k<<<dim3(NCH, BATCH), DIN>>>(u, xd, Abm, dtw, dtb, hp, flm);
        scan2_k<<<32, 256>>>(hp);
        scan3_k<<<dim3(NCH, BATCH), DIN>>>(u, xd, xr, Abm, dtw, dtb, Dp, hp, yg, flm);
        // out_proj + LayerNorm (+ transpose on final)
        gemm64_k<<<dim3(SEQL / 64, 1, BATCH), 256>>>(yg, wot + m*8192, gout, 128, 64, 64,
                                                     (long)SEQL * DIN, DIN, 1, 2, lng, lnb, trans);
    }
}

// round 3
// speedup vs baseline: 1.3313x; 1.2866x over previous
#include <cuda_runtime.h>

#define BATCH 4
#define SEQL  4096
#define DIN   128
#define NST   16
#define TCH   32
#define NCH   128   /* SEQL / TCH */

typedef unsigned long long u64;

#define FMA2(d, a, b, c) asm("fma.rn.f32x2 %0, %1, %2, %3;" : "=l"(d) : "l"(a), "l"(b), "l"(c))
#define MUL2(d, a, b)    asm("mul.rn.f32x2 %0, %1, %2;" : "=l"(d) : "l"(a), "l"(b))
#define UNPK2(x, y, in)  asm("mov.b64 {%0, %1}, %2;" : "=f"(x), "=f"(y) : "l"(in))
#define PK1(d, x)        asm("mov.b64 %0, {%1, %1};" : "=l"(d) : "f"(x))
#define PKP(d, x, y)     asm("mov.b64 %0, {%1, %2};" : "=l"(d) : "f"(x), "f"(y))

// ---------------- scratch (device globals; no allocation) ----------------
__device__ float g_xr  [BATCH*SEQL*256];   // in_proj output (u | res), row-major [l][256]
__device__ float g_u   [BATCH*DIN*SEQL];   // silu(conv(u)), k-major [b][d][l]
__device__ float g_xdbl[BATCH*SEQL*36];    // x_proj output, row-major [l][36] (dt4|B16|C16)
__device__ float g_hp  [BATCH*NCH*DIN*32]; // per-chunk [h_end(16)|P(16)] -> H_init
__device__ float g_yg  [BATCH*DIN*SEQL];   // gated scan output, k-major [b][d][l]
__device__ float g_xmid[BATCH*64*SEQL];    // between mambas, k-major [b][c][l]
__device__ float g_w1t [2][64*256];        // in_proj W transposed [k][n]
__device__ float g_wxt [2][128*64];        // x_proj W transposed, zero-padded to 64
__device__ float g_wot [2][128*64];        // out_proj W transposed
__device__ float g_Ab  [2][DIN*NST];       // A = -exp(Alog)
__device__ int   g_Afl [2];                // 1 if A[d][n] == (n+1)*A[d][0]

__device__ __forceinline__ float softplusf(float x) {
    return x > 15.f ? x : __logf(1.f + __expf(x));
}
__device__ __forceinline__ float siluf(float x) {
    return x / (1.f + __expf(-x));
}

// ---------------- prep ----------------
__global__ void prep_k(const float* __restrict__ in_w, const float* __restrict__ xproj,
                       const float* __restrict__ out_w, const float* __restrict__ Alog,
                       float* __restrict__ w1t, float* __restrict__ wxt,
                       float* __restrict__ wot, float* __restrict__ Ab) {
    int idx = blockIdx.x * 256 + threadIdx.x;
    if (idx < 16384) { int k = idx >> 8, n = idx & 255; w1t[idx] = in_w[n*64 + k]; return; }
    idx -= 16384;
    if (idx < 8192)  { int k = idx >> 6, n = idx & 63; wxt[idx] = (n < 36) ? xproj[n*128 + k] : 0.f; return; }
    idx -= 8192;
    if (idx < 8192)  { int k = idx >> 6, n = idx & 63; wot[idx] = out_w[n*128 + k]; return; }
    idx -= 8192;
    if (idx < 2048)  Ab[idx] = -expf(Alog[idx]);
}

__global__ void chkA_k(const float* __restrict__ A0, const float* __restrict__ A1,
                       int* __restrict__ fl) {
    const float* A = blockIdx.x ? A1 : A0;
    __shared__ int ok;
    if (threadIdx.x == 0) ok = 1;
    __syncthreads();
    int bad = 0;
    for (int e = threadIdx.x; e < DIN*NST; e += 256) {
        int d = e >> 4, n = e & 15;
        float expv = (float)(n + 1) * A[d*16];
        if (fabsf(A[e] - expv) > 1e-5f * fabsf(expv) + 1e-20f) bad = 1;
    }
    if (bad) atomicAnd(&ok, 0);
    __syncthreads();
    if (threadIdx.x == 0) fl[blockIdx.x] = ok;
}

// ---------------- GEMM: X k-major [b][K][4096]; tile 128L x 64N; 8Lx4N/thread ----------------
// epi: 0 = row-major write [l][Nout] at col n0; 1 = cols<36 to [l][36];
//      2 = LayerNorm over 64 cols + TRANSPOSED write [b][64][4096].
__global__ __launch_bounds__(256) void gemm_k(
    const float* __restrict__ X, const float* __restrict__ Wt, float* __restrict__ Out,
    int K, int Nld, int Nout, int epi,
    const float* __restrict__ lng, const float* __restrict__ lnb)
{
    extern __shared__ float sm[];
    float* xs = sm;             // [K][128]
    float* ws = sm + K * 128;   // [K][64]
    int tid = threadIdx.x;
    int l0 = blockIdx.x << 7;
    int n0 = blockIdx.y << 6;
    int b  = blockIdx.z;
    const float* Xb = X + (long)b * K * SEQL;
    int lj = tid >> 4, ng = tid & 15;
    int lb = lj << 3;

    // load W tile [K][64]
    int witer = K >> 4;
    for (int i = 0; i < witer; i++) {
        int s = tid + (i << 8);
        int k = s >> 4, nq = s & 15;
        *(float4*)&ws[k*64 + (nq<<2)] = *(const float4*)&Wt[(long)k*Nld + n0 + (nq<<2)];
    }
    // load X tile [K][128]
    int xiter = K >> 3;
    for (int i = 0; i < xiter; i++) {
        int s = tid + (i << 8);
        int k = s >> 5, lq = s & 31;
        *(float4*)&xs[k*128 + (lq<<2)] = *(const float4*)&Xb[(long)k*SEQL + l0 + (lq<<2)];
    }
    __syncthreads();

    u64 acc[4][4];  // [row-pair p: rows 2p,2p+1][col c]
#pragma unroll
    for (int p = 0; p < 4; p++)
#pragma unroll
        for (int c = 0; c < 4; c++) acc[p][c] = 0ULL;

#pragma unroll 8
    for (int kk = 0; kk < K; kk++) {
        ulonglong2 a01 = *(const ulonglong2*)&xs[kk*128 + lb];       // rows (0,1),(2,3)
        ulonglong2 a23 = *(const ulonglong2*)&xs[kk*128 + lb + 4];   // rows (4,5),(6,7)
        float4 wv = *(const float4*)&ws[kk*64 + (ng<<2)];
        u64 b0, b1, b2, b3;
        PK1(b0, wv.x); PK1(b1, wv.y); PK1(b2, wv.z); PK1(b3, wv.w);
        FMA2(acc[0][0], a01.x, b0, acc[0][0]); FMA2(acc[0][1], a01.x, b1, acc[0][1]);
        FMA2(acc[0][2], a01.x, b2, acc[0][2]); FMA2(acc[0][3], a01.x, b3, acc[0][3]);
        FMA2(acc[1][0], a01.y, b0, acc[1][0]); FMA2(acc[1][1], a01.y, b1, acc[1][1]);
        FMA2(acc[1][2], a01.y, b2, acc[1][2]); FMA2(acc[1][3], a01.y, b3, acc[1][3]);
        FMA2(acc[2][0], a23.x, b0, acc[2][0]); FMA2(acc[2][1], a23.x, b1, acc[2][1]);
        FMA2(acc[2][2], a23.x, b2, acc[2][2]); FMA2(acc[2][3], a23.x, b3, acc[2][3]);
        FMA2(acc[3][0], a23.y, b0, acc[3][0]); FMA2(acc[3][1], a23.y, b1, acc[3][1]);
        FMA2(acc[3][2], a23.y, b2, acc[3][2]); FMA2(acc[3][3], a23.y, b3, acc[3][3]);
    }

    if (epi == 0) {
#pragma unroll
        for (int p = 0; p < 4; p++) {
            float lo[4], hi[4];
#pragma unroll
            for (int c = 0; c < 4; c++) UNPK2(lo[c], hi[c], acc[p][c]);
            long r0 = ((long)b*SEQL + l0 + lb + 2*p) * Nout + n0 + (ng<<2);
            *(float4*)&Out[r0]        = make_float4(lo[0], lo[1], lo[2], lo[3]);
            *(float4*)&Out[r0 + Nout] = make_float4(hi[0], hi[1], hi[2], hi[3]);
        }
    } else if (epi == 1) {
        if (ng < 9) {
#pragma unroll
            for (int p = 0; p < 4; p++) {
                float lo[4], hi[4];
#pragma unroll
                for (int c = 0; c < 4; c++) UNPK2(lo[c], hi[c], acc[p][c]);
                long r0 = ((long)b*SEQL + l0 + lb + 2*p) * 36 + (ng<<2);
                *(float4*)&Out[r0]      = make_float4(lo[0], lo[1], lo[2], lo[3]);
                *(float4*)&Out[r0 + 36] = make_float4(hi[0], hi[1], hi[2], hi[3]);
            }
        }
    } else {
        // LayerNorm over 64 cols + transposed coalesced write (n0==0, K==128)
        float* st  = sm;              // [128][66]
        float* st2 = sm + 128*66;     // [64][129]
        __syncthreads();
#pragma unroll
        for (int p = 0; p < 4; p++) {
#pragma unroll
            for (int c = 0; c < 4; c++) {
                float lo, hi;
                UNPK2(lo, hi, acc[p][c]);
                st[(lb + 2*p)*66 + (ng<<2) + c]     = lo;
                st[(lb + 2*p + 1)*66 + (ng<<2) + c] = hi;
            }
        }
        __syncthreads();
        int row = tid >> 1, q = tid & 1;
        float v[32], s = 0.f, s2 = 0.f;
#pragma unroll
        for (int j = 0; j < 32; j++) {
            float x = st[row*66 + q*32 + j];
            v[j] = x; s += x; s2 += x * x;
        }
        s  += __shfl_xor_sync(0xffffffffu, s, 1);
        s2 += __shfl_xor_sync(0xffffffffu, s2, 1);
        float mean = s * 0.015625f;
        float var  = s2 * 0.015625f - mean * mean;
        float rstd = rsqrtf(var + 1e-5f);
#pragma unroll
        for (int j = 0; j < 32; j++) {
            int n = q*32 + j;
            st2[n*129 + row] = (v[j] - mean) * rstd * __ldg(&lng[n]) + __ldg(&lnb[n]);
        }
        __syncthreads();
        int n2 = tid >> 2, lq = tid & 3;
#pragma unroll
        for (int i = 0; i < 8; i++) {
            int l = (lq << 5) + (i << 2);
            float4 o4 = make_float4(st2[n2*129 + l], st2[n2*129 + l + 1],
                                    st2[n2*129 + l + 2], st2[n2*129 + l + 3]);
            *(float4*)&Out[((long)b*64 + n2)*SEQL + l0 + l] = o4;
        }
    }
}

// ---------------- causal depthwise conv (k=4) + silu; out k-major [b][d][l] ----------------
__global__ __launch_bounds__(256) void conv_silu_k(const float* __restrict__ xr,
                                                   const float* __restrict__ cw,
                                                   const float* __restrict__ cb,
                                                   float* __restrict__ u) {
    __shared__ float sx[35*132];
    __shared__ float su[32*129];
    int tid = threadIdx.x;
    int l0 = blockIdx.x << 5;
    int b  = blockIdx.y;
    for (int e = tid; e < 35*128; e += 256) {
        int row = e >> 7, dd = e & 127;
        int lg = l0 - 3 + row;
        sx[row*132 + dd] = (lg >= 0) ? xr[((long)b*SEQL + lg)*256 + dd] : 0.f;
    }
    __syncthreads();
    int d = tid >> 1, half = tid & 1;
    float4 w = *(const float4*)&cw[d*4];
    float bias = __ldg(&cb[d]);
#pragma unroll
    for (int j = 0; j < 16; j++) {
        int l = half*16 + j;
        float s = bias + w.w*sx[(l+3)*132 + d] + w.z*sx[(l+2)*132 + d]
                       + w.y*sx[(l+1)*132 + d] + w.x*sx[l*132 + d];
        su[l*129 + d] = siluf(s);
    }
    __syncthreads();
    for (int e = tid; e < 4096; e += 256) {
        int d2 = e >> 5, li = e & 31;
        u[((long)b*DIN + d2)*SEQL + l0 + li] = su[li*129 + d2];
    }
}

// ---------------- scan pass 1 ----------------
__global__ __launch_bounds__(128) void scan1_k(const float* __restrict__ u,
                                               const float* __restrict__ xdbl,
                                               const float* __restrict__ Ap,
                                               const float* __restrict__ dtw,
                                               const float* __restrict__ dtb,
                                               float* __restrict__ hp,
                                               const int* __restrict__ flagp) {
    __shared__ float xds[TCH*36];
    __shared__ float us[TCH*129];
    int d = threadIdx.x;
    int c = blockIdx.x, b = blockIdx.y;
    long lc = (long)b*SEQL + c*TCH;
    for (int e = d; e < TCH*36; e += 128) xds[e] = xdbl[lc*36 + e];
    for (int e = d; e < TCH*DIN; e += 128) {
        int d2 = e >> 5, t = e & 31;
        us[t*129 + d2] = u[((long)b*DIN + d2)*SEQL + c*TCH + t];
    }
    float4 w = *(const float4*)&dtw[d*4];
    float bias = __ldg(&dtb[d]);
    int structured = *flagp;
    float A0 = Ap[d*NST];
    float S = 0.f;
    float* o = hp + (((long)b*NCH + c)*DIN + d)*32;
    __syncthreads();
    if (structured) {
        u64 h2[8];
#pragma unroll
        for (int p = 0; p < 8; p++) h2[p] = 0ULL;
        for (int t = 0; t < TCH; t++) {
            const float* xt = xds + t*36;
            float dt = fmaf(xt[0], w.x, fmaf(xt[1], w.y, fmaf(xt[2], w.z, fmaf(xt[3], w.w, bias))));
            dt = softplusf(dt);
            S += dt;
            float du = dt * us[t*129 + d];
            float r = __expf(dt * A0);
            float r2 = r * r;
            u64 a2, rr2, du2;
            PKP(a2, r, r2); PK1(rr2, r2); PK1(du2, du);
#pragma unroll
            for (int p = 0; p < 8; p++) {
                u64 bp = *(const u64*)&xt[4 + 2*p];
                u64 m;
                MUL2(m, du2, bp);
                FMA2(h2[p], a2, h2[p], m);
                if (p < 7) MUL2(a2, a2, rr2);
            }
        }
#pragma unroll
        for (int p = 0; p < 8; p++) *(u64*)&o[2*p] = h2[p];
        float q = __expf(S * A0), qc = q;
#pragma unroll
        for (int n = 0; n < NST; n++) { o[16 + n] = qc; qc *= q; }
    } else {
        float Ar[NST], h[NST];
#pragma unroll
        for (int n = 0; n < NST; n++) { Ar[n] = Ap[d*NST + n]; h[n] = 0.f; }
        for (int t = 0; t < TCH; t++) {
            const float* xt = xds + t*36;
            float dt = fmaf(xt[0], w.x, fmaf(xt[1], w.y, fmaf(xt[2], w.z, fmaf(xt[3], w.w, bias))));
            dt = softplusf(dt);
            S += dt;
            float du = dt * us[t*129 + d];
#pragma unroll
            for (int n = 0; n < NST; n++) {
                float a = __expf(dt * Ar[n]);
                h[n] = fmaf(a, h[n], du * xt[4 + n]);
            }
        }
#pragma unroll
        for (int n = 0; n < NST; n++) { o[n] = h[n]; o[16 + n] = __expf(S * Ar[n]); }
    }
}

// ---------------- scan pass 2: sequential chunk combine ----------------
__global__ void scan2_k(float* __restrict__ hp) {
    int idx = blockIdx.x * 256 + threadIdx.x;   // 8192 threads
    int dn = idx & 2047;
    int b = idx >> 11;
    int off = ((dn >> 4) << 5) + (dn & 15);
    long base = (long)b * NCH * (DIN*32) + off;
    float H = 0.f;
    for (int c = 0; c < NCH; c++) {
        float he = hp[base];
        float p  = hp[base + 16];
        hp[base] = H;
        H = fmaf(p, H, he);
        base += DIN*32;
    }
}

// ---------------- scan pass 3: replay + gate; out k-major [b][d][l] ----------------
__global__ __launch_bounds__(128) void scan3_k(const float* __restrict__ u,
                                               const float* __restrict__ xdbl,
                                               const float* __restrict__ xr,
                                               const float* __restrict__ Ap,
                                               const float* __restrict__ dtw,
                                               const float* __restrict__ dtb,
                                               const float* __restrict__ Dp,
                                               const float* __restrict__ hp,
                                               float* __restrict__ yg,
                                               const int* __restrict__ flagp) {
    __shared__ float xds[TCH*36];
    __shared__ float us[TCH*129];
    __shared__ float ys[TCH*129];
    int d = threadIdx.x;
    int c = blockIdx.x, b = blockIdx.y;
    long lc = (long)b*SEQL + c*TCH;
    for (int e = d; e < TCH*36; e += 128) xds[e] = xdbl[lc*36 + e];
    for (int e = d; e < TCH*DIN; e += 128) {
        int d2 = e >> 5, t = e & 31;
        us[t*129 + d2] = u[((long)b*DIN + d2)*SEQL + c*TCH + t];
    }
    float4 w = *(const float4*)&dtw[d*4];
    float bias = __ldg(&dtb[d]);
    float Dd = __ldg(&Dp[d]);
    int structured = *flagp;
    float A0 = Ap[d*NST];
    const float* hi = hp + (((long)b*NCH + c)*DIN + d)*32;
    __syncthreads();
    if (structured) {
        u64 h2[8];
#pragma unroll
        for (int p = 0; p < 8; p++) h2[p] = *(const u64*)&hi[2*p];
        for (int t = 0; t < TCH; t++) {
            const float* xt = xds + t*36;
            float dt = fmaf(xt[0], w.x, fmaf(xt[1], w.y, fmaf(xt[2], w.z, fmaf(xt[3], w.w, bias))));
            dt = softplusf(dt);
            float ut = us[t*129 + d];
            float du = dt * ut;
            float r = __expf(dt * A0);
            float r2 = r * r;
            u64 a2, rr2, du2, y2 = 0ULL;
            PKP(a2, r, r2); PK1(rr2, r2); PK1(du2, du);
#pragma unroll
            for (int p = 0; p < 8; p++) {
                u64 bp = *(const u64*)&xt[4 + 2*p];
                u64 cp = *(const u64*)&xt[20 + 2*p];
                u64 m;
                MUL2(m, du2, bp);
                FMA2(h2[p], a2, h2[p], m);
                FMA2(y2, h2[p], cp, y2);
                if (p < 7) MUL2(a2, a2, rr2);
            }
            float ylo, yhi;
            UNPK2(ylo, yhi, y2);
            float rt = xr[(lc + t)*256 + 128 + d];
            ys[t*129 + d] = fmaf(ut, Dd, ylo + yhi) * siluf(rt);
        }
    } else {
        float Ar[NST], h[NST];
#pragma unroll
        for (int n = 0; n < NST; n++) { Ar[n] = Ap[d*NST + n]; h[n] = hi[n]; }
        for (int t = 0; t < TCH; t++) {
            const float* xt = xds + t*36;
            float dt = fmaf(xt[0], w.x, fmaf(xt[1], w.y, fmaf(xt[2], w.z, fmaf(xt[3], w.w, bias))));
            dt = softplusf(dt);
            float ut = us[t*129 + d];
            float du = dt * ut;
            float y = 0.f;
#pragma unroll
            for (int n = 0; n < NST; n++) {
                float a = __expf(dt * Ar[n]);
                h[n] = fmaf(a, h[n], du * xt[4 + n]);
                y = fmaf(h[n], xt[20 + n], y);
            }
            float rt = xr[(lc + t)*256 + 128 + d];
            ys[t*129 + d] = fmaf(ut, Dd, y) * siluf(rt);
        }
    }
    __syncthreads();
    for (int e = d; e < TCH*DIN; e += 128) {
        int d2 = e >> 5, t = e & 31;
        yg[((long)b*DIN + d2)*SEQL + c*TCH + t] = ys[t*129 + d2];
    }
}

// ---------------- host ----------------
extern "C" void kernel_launch(void* const* d_in, const int* in_sizes, int n_in,
                              void* d_out, int out_size) {
    const float* x1 = (const float*)d_in[0];
    float* out = (float*)d_out;

    float *xr, *u, *xd, *hp, *yg, *xmid, *w1t, *wxt, *wot, *Ab;
    int* Afl;
    cudaGetSymbolAddress((void**)&xr,   g_xr);
    cudaGetSymbolAddress((void**)&u,    g_u);
    cudaGetSymbolAddress((void**)&xd,   g_xdbl);
    cudaGetSymbolAddress((void**)&hp,   g_hp);
    cudaGetSymbolAddress((void**)&yg,   g_yg);
    cudaGetSymbolAddress((void**)&xmid, g_xmid);
    cudaGetSymbolAddress((void**)&w1t,  g_w1t);
    cudaGetSymbolAddress((void**)&wxt,  g_wxt);
    cudaGetSymbolAddress((void**)&wot,  g_wot);
    cudaGetSymbolAddress((void**)&Ab,   g_Ab);
    cudaGetSymbolAddress((void**)&Afl,  g_Afl);

    cudaFuncSetAttribute(gemm_k, cudaFuncAttributeMaxDynamicSharedMemorySize, 128*192*4);

    for (int m = 0; m < 2; m++) {
        prep_k<<<136, 256>>>((const float*)d_in[1 + 9*m + 0], (const float*)d_in[1 + 9*m + 3],
                             (const float*)d_in[1 + 9*m + 8], (const float*)d_in[1 + 9*m + 6],
                             w1t + m*16384, wxt + m*8192, wot + m*8192, Ab + m*2048);
    }
    chkA_k<<<2, 256>>>(Ab, Ab + 2048, Afl);

    for (int m = 0; m < 2; m++) {
        const float* cw  = (const float*)d_in[1 + 9*m + 1];
        const float* cb  = (const float*)d_in[1 + 9*m + 2];
        const float* dtw = (const float*)d_in[1 + 9*m + 4];
        const float* dtb = (const float*)d_in[1 + 9*m + 5];
        const float* Dp  = (const float*)d_in[1 + 9*m + 7];
        const float* lng = (const float*)d_in[19 + 2*m];
        const float* lnb = (const float*)d_in[20 + 2*m];
        const float* Abm = Ab + m*2048;
        const int*   flm = Afl + m;

        const float* Xin = (m == 0) ? x1 : xmid;      // k-major [b][64][4096]
        float* gout = (m == 0) ? xmid : out;          // k-major [b][64][4096]

        // in_proj: K=64, N=256, row-major out xr
        gemm_k<<<dim3(SEQL/128, 4, BATCH), 256, 64*192*4>>>(
            Xin, w1t + m*16384, xr, 64, 256, 256, 0, nullptr, nullptr);
        // conv + silu -> u [b][128][4096]
        conv_silu_k<<<dim3(SEQL/32, BATCH), 256>>>(xr, cw, cb, u);
        // x_proj: K=128, N=64(36), row-major out xd
        gemm_k<<<dim3(SEQL/128, 1, BATCH), 256, 128*192*4>>>(
            u, wxt + m*8192, xd, 128, 64, 36, 1, nullptr, nullptr);
        // chunked selective scan
        scan1_k<<<dim3(NCH, BATCH), DIN>>>(u, xd, Abm, dtw, dtb, hp, flm);
        scan2_k<<<32, 256>>>(hp);
        scan3_k<<<dim3(NCH, BATCH), DIN>>>(u, xd, xr, Abm, dtw, dtb, Dp, hp, yg, flm);
        // out_proj + LayerNorm + transposed write
        gemm_k<<<dim3(SEQL/128, 1, BATCH), 256, 128*192*4>>>(
            yg, wot + m*8192, gout, 128, 64, 64, 2, lng, lnb);
    }
}

// round 4
// speedup vs baseline: 1.3349x; 1.0027x over previous
#include <cuda_runtime.h>

#define BATCH 4
#define SEQL  4096
#define DIN   128
#define NST   16
#define TCH   32
#define NCH   128   /* SEQL / TCH */

typedef unsigned long long u64;

#define FMA2(d, a, b, c) asm("fma.rn.f32x2 %0, %1, %2, %3;" : "=l"(d) : "l"(a), "l"(b), "l"(c))
#define MUL2(d, a, b)    asm("mul.rn.f32x2 %0, %1, %2;" : "=l"(d) : "l"(a), "l"(b))
#define UNPK2(x, y, in)  asm("mov.b64 {%0, %1}, %2;" : "=f"(x), "=f"(y) : "l"(in))
#define PK1(d, x)        asm("mov.b64 %0, {%1, %1};" : "=l"(d) : "f"(x))
#define PKP(d, x, y)     asm("mov.b64 %0, {%1, %2};" : "=l"(d) : "f"(x), "f"(y))

// ---------------- scratch (device globals; no allocation) ----------------
__device__ float g_xr  [BATCH*SEQL*256];   // in_proj output (u | res), row-major [l][256]
__device__ float g_u   [BATCH*DIN*SEQL];   // silu(conv(u)), k-major [b][d][l]
__device__ float g_xdbl[BATCH*SEQL*36];    // x_proj output, row-major [l][36] (dt4|B16|C16)
__device__ float g_hp  [BATCH*NCH*DIN*32]; // per-chunk [h_end(16)|P(16)] -> H_init
__device__ float g_yg  [BATCH*DIN*SEQL];   // gated scan output, k-major [b][d][l]
__device__ float g_xmid[BATCH*64*SEQL];    // between mambas, k-major [b][c][l]
__device__ float g_w1t [2][64*256];        // in_proj W transposed [k][n]
__device__ float g_wxt [2][128*64];        // x_proj W transposed, zero-padded to 64
__device__ float g_wot [2][128*64];        // out_proj W transposed
__device__ float g_Ab  [2][DIN*NST];       // A = -exp(Alog)
__device__ int   g_Afl [2];                // 1 if A[d][n] == (n+1)*A[d][0]

__device__ __forceinline__ float softplusf(float x) {
    return x > 15.f ? x : __logf(1.f + __expf(x));
}
__device__ __forceinline__ float siluf(float x) {
    return x / (1.f + __expf(-x));
}

// ---------------- prep ----------------
__global__ void prep_k(const float* __restrict__ in_w, const float* __restrict__ xproj,
                       const float* __restrict__ out_w, const float* __restrict__ Alog,
                       float* __restrict__ w1t, float* __restrict__ wxt,
                       float* __restrict__ wot, float* __restrict__ Ab) {
    int idx = blockIdx.x * 256 + threadIdx.x;
    if (idx < 16384) { int k = idx >> 8, n = idx & 255; w1t[idx] = in_w[n*64 + k]; return; }
    idx -= 16384;
    if (idx < 8192)  { int k = idx >> 6, n = idx & 63; wxt[idx] = (n < 36) ? xproj[n*128 + k] : 0.f; return; }
    idx -= 8192;
    if (idx < 8192)  { int k = idx >> 6, n = idx & 63; wot[idx] = out_w[n*128 + k]; return; }
    idx -= 8192;
    if (idx < 2048)  Ab[idx] = -expf(Alog[idx]);
}

__global__ void chkA_k(const float* __restrict__ A0, const float* __restrict__ A1,
                       int* __restrict__ fl) {
    const float* A = blockIdx.x ? A1 : A0;
    __shared__ int ok;
    if (threadIdx.x == 0) ok = 1;
    __syncthreads();
    int bad = 0;
    for (int e = threadIdx.x; e < DIN*NST; e += 256) {
        int d = e >> 4, n = e & 15;
        float expv = (float)(n + 1) * A[d*16];
        if (fabsf(A[e] - expv) > 1e-5f * fabsf(expv) + 1e-20f) bad = 1;
    }
    if (bad) atomicAnd(&ok, 0);
    __syncthreads();
    if (threadIdx.x == 0) fl[blockIdx.x] = ok;
}

// ---------------- GEMM: X k-major [b][K][4096]; tile 128L x 64N; 8Lx4N/thread ----------------
// epi: 0 = row-major write [l][Nout] at col n0; 1 = cols<36 to [l][36];
//      2 = LayerNorm over 64 cols + TRANSPOSED write [b][64][4096].
__global__ __launch_bounds__(256) void gemm_k(
    const float* __restrict__ X, const float* __restrict__ Wt, float* __restrict__ Out,
    int K, int Nld, int Nout, int epi,
    const float* __restrict__ lng, const float* __restrict__ lnb)
{
    extern __shared__ float sm[];
    float* xs = sm;             // [K][128]
    float* ws = sm + K * 128;   // [K][64]
    int tid = threadIdx.x;
    int l0 = blockIdx.x << 7;
    int n0 = blockIdx.y << 6;
    int b  = blockIdx.z;
    const float* Xb = X + (long)b * K * SEQL;
    int lj = tid >> 4, ng = tid & 15;
    int lb = lj << 3;

    // load W tile [K][64]
    int witer = K >> 4;
    for (int i = 0; i < witer; i++) {
        int s = tid + (i << 8);
        int k = s >> 4, nq = s & 15;
        *(float4*)&ws[k*64 + (nq<<2)] = *(const float4*)&Wt[(long)k*Nld + n0 + (nq<<2)];
    }
    // load X tile [K][128]
    int xiter = K >> 3;
    for (int i = 0; i < xiter; i++) {
        int s = tid + (i << 8);
        int k = s >> 5, lq = s & 31;
        *(float4*)&xs[k*128 + (lq<<2)] = *(const float4*)&Xb[(long)k*SEQL + l0 + (lq<<2)];
    }
    __syncthreads();

    u64 acc[4][4];  // [row-pair p: rows 2p,2p+1][col c]
#pragma unroll
    for (int p = 0; p < 4; p++)
#pragma unroll
        for (int c = 0; c < 4; c++) acc[p][c] = 0ULL;

#pragma unroll 8
    for (int kk = 0; kk < K; kk++) {
        ulonglong2 a01 = *(const ulonglong2*)&xs[kk*128 + lb];       // rows (0,1),(2,3)
        ulonglong2 a23 = *(const ulonglong2*)&xs[kk*128 + lb + 4];   // rows (4,5),(6,7)
        float4 wv = *(const float4*)&ws[kk*64 + (ng<<2)];
        u64 b0, b1, b2, b3;
        PK1(b0, wv.x); PK1(b1, wv.y); PK1(b2, wv.z); PK1(b3, wv.w);
        FMA2(acc[0][0], a01.x, b0, acc[0][0]); FMA2(acc[0][1], a01.x, b1, acc[0][1]);
        FMA2(acc[0][2], a01.x, b2, acc[0][2]); FMA2(acc[0][3], a01.x, b3, acc[0][3]);
        FMA2(acc[1][0], a01.y, b0, acc[1][0]); FMA2(acc[1][1], a01.y, b1, acc[1][1]);
        FMA2(acc[1][2], a01.y, b2, acc[1][2]); FMA2(acc[1][3], a01.y, b3, acc[1][3]);
        FMA2(acc[2][0], a23.x, b0, acc[2][0]); FMA2(acc[2][1], a23.x, b1, acc[2][1]);
        FMA2(acc[2][2], a23.x, b2, acc[2][2]); FMA2(acc[2][3], a23.x, b3, acc[2][3]);
        FMA2(acc[3][0], a23.y, b0, acc[3][0]); FMA2(acc[3][1], a23.y, b1, acc[3][1]);
        FMA2(acc[3][2], a23.y, b2, acc[3][2]); FMA2(acc[3][3], a23.y, b3, acc[3][3]);
    }

    if (epi == 0) {
#pragma unroll
        for (int p = 0; p < 4; p++) {
            float lo[4], hi[4];
#pragma unroll
            for (int c = 0; c < 4; c++) UNPK2(lo[c], hi[c], acc[p][c]);
            long r0 = ((long)b*SEQL + l0 + lb + 2*p) * Nout + n0 + (ng<<2);
            *(float4*)&Out[r0]        = make_float4(lo[0], lo[1], lo[2], lo[3]);
            *(float4*)&Out[r0 + Nout] = make_float4(hi[0], hi[1], hi[2], hi[3]);
        }
    } else if (epi == 1) {
        if (ng < 9) {
#pragma unroll
            for (int p = 0; p < 4; p++) {
                float lo[4], hi[4];
#pragma unroll
                for (int c = 0; c < 4; c++) UNPK2(lo[c], hi[c], acc[p][c]);
                long r0 = ((long)b*SEQL + l0 + lb + 2*p) * 36 + (ng<<2);
                *(float4*)&Out[r0]      = make_float4(lo[0], lo[1], lo[2], lo[3]);
                *(float4*)&Out[r0 + 36] = make_float4(hi[0], hi[1], hi[2], hi[3]);
            }
        }
    } else {
        // LayerNorm over 64 cols + transposed coalesced write (n0==0, K==128)
        float* st  = sm;              // [128][66]
        float* st2 = sm + 128*66;     // [64][129]
        __syncthreads();
#pragma unroll
        for (int p = 0; p < 4; p++) {
#pragma unroll
            for (int c = 0; c < 4; c++) {
                float lo, hi;
                UNPK2(lo, hi, acc[p][c]);
                st[(lb + 2*p)*66 + (ng<<2) + c]     = lo;
                st[(lb + 2*p + 1)*66 + (ng<<2) + c] = hi;
            }
        }
        __syncthreads();
        int row = tid >> 1, q = tid & 1;
        float v[32], s = 0.f, s2 = 0.f;
#pragma unroll
        for (int j = 0; j < 32; j++) {
            float x = st[row*66 + q*32 + j];
            v[j] = x; s += x; s2 += x * x;
        }
        s  += __shfl_xor_sync(0xffffffffu, s, 1);
        s2 += __shfl_xor_sync(0xffffffffu, s2, 1);
        float mean = s * 0.015625f;
        float var  = s2 * 0.015625f - mean * mean;
        float rstd = rsqrtf(var + 1e-5f);
#pragma unroll
        for (int j = 0; j < 32; j++) {
            int n = q*32 + j;
            st2[n*129 + row] = (v[j] - mean) * rstd * __ldg(&lng[n]) + __ldg(&lnb[n]);
        }
        __syncthreads();
        int n2 = tid >> 2, lq = tid & 3;
#pragma unroll
        for (int i = 0; i < 8; i++) {
            int l = (lq << 5) + (i << 2);
            float4 o4 = make_float4(st2[n2*129 + l], st2[n2*129 + l + 1],
                                    st2[n2*129 + l + 2], st2[n2*129 + l + 3]);
            *(float4*)&Out[((long)b*64 + n2)*SEQL + l0 + l] = o4;
        }
    }
}

// ---------------- causal depthwise conv (k=4) + silu; out k-major [b][d][l] ----------------
__global__ __launch_bounds__(256) void conv_silu_k(const float* __restrict__ xr,
                                                   const float* __restrict__ cw,
                                                   const float* __restrict__ cb,
                                                   float* __restrict__ u) {
    __shared__ float sx[35*132];
    __shared__ float su[32*129];
    int tid = threadIdx.x;
    int l0 = blockIdx.x << 5;
    int b  = blockIdx.y;
    for (int e = tid; e < 35*128; e += 256) {
        int row = e >> 7, dd = e & 127;
        int lg = l0 - 3 + row;
        sx[row*132 + dd] = (lg >= 0) ? xr[((long)b*SEQL + lg)*256 + dd] : 0.f;
    }
    __syncthreads();
    int d = tid >> 1, half = tid & 1;
    float4 w = *(const float4*)&cw[d*4];
    float bias = __ldg(&cb[d]);
#pragma unroll
    for (int j = 0; j < 16; j++) {
        int l = half*16 + j;
        float s = bias + w.w*sx[(l+3)*132 + d] + w.z*sx[(l+2)*132 + d]
                       + w.y*sx[(l+1)*132 + d] + w.x*sx[l*132 + d];
        su[l*129 + d] = siluf(s);
    }
    __syncthreads();
    for (int e = tid; e < 4096; e += 256) {
        int d2 = e >> 5, li = e & 31;
        u[((long)b*DIN + d2)*SEQL + l0 + li] = su[li*129 + d2];
    }
}

// ---------------- scan pass 1 ----------------
__global__ __launch_bounds__(128) void scan1_k(const float* __restrict__ u,
                                               const float* __restrict__ xdbl,
                                               const float* __restrict__ Ap,
                                               const float* __restrict__ dtw,
                                               const float* __restrict__ dtb,
                                               float* __restrict__ hp,
                                               const int* __restrict__ flagp) {
    __shared__ float xds[TCH*36];
    __shared__ float us[TCH*129];
    int d = threadIdx.x;
    int c = blockIdx.x, b = blockIdx.y;
    long lc = (long)b*SEQL + c*TCH;
    for (int e = d; e < TCH*36; e += 128) xds[e] = xdbl[lc*36 + e];
    for (int e = d; e < TCH*DIN; e += 128) {
        int d2 = e >> 5, t = e & 31;
        us[t*129 + d2] = u[((long)b*DIN + d2)*SEQL + c*TCH + t];
    }
    float4 w = *(const float4*)&dtw[d*4];
    float bias = __ldg(&dtb[d]);
    int structured = *flagp;
    float A0 = Ap[d*NST];
    float S = 0.f;
    float* o = hp + (((long)b*NCH + c)*DIN + d)*32;
    __syncthreads();
    if (structured) {
        u64 h2[8];
#pragma unroll
        for (int p = 0; p < 8; p++) h2[p] = 0ULL;
        for (int t = 0; t < TCH; t++) {
            const float* xt = xds + t*36;
            float dt = fmaf(xt[0], w.x, fmaf(xt[1], w.y, fmaf(xt[2], w.z, fmaf(xt[3], w.w, bias))));
            dt = softplusf(dt);
            S += dt;
            float du = dt * us[t*129 + d];
            float r = __expf(dt * A0);
            float r2 = r * r;
            u64 a2, rr2, du2;
            PKP(a2, r, r2); PK1(rr2, r2); PK1(du2, du);
#pragma unroll
            for (int p = 0; p < 8; p++) {
                u64 bp = *(const u64*)&xt[4 + 2*p];
                u64 m;
                MUL2(m, du2, bp);
                FMA2(h2[p], a2, h2[p], m);
                if (p < 7) MUL2(a2, a2, rr2);
            }
        }
#pragma unroll
        for (int p = 0; p < 8; p++) *(u64*)&o[2*p] = h2[p];
        float q = __expf(S * A0), qc = q;
#pragma unroll
        for (int n = 0; n < NST; n++) { o[16 + n] = qc; qc *= q; }
    } else {
        float Ar[NST], h[NST];
#pragma unroll
        for (int n = 0; n < NST; n++) { Ar[n] = Ap[d*NST + n]; h[n] = 0.f; }
        for (int t = 0; t < TCH; t++) {
            const float* xt = xds + t*36;
            float dt = fmaf(xt[0], w.x, fmaf(xt[1], w.y, fmaf(xt[2], w.z, fmaf(xt[3], w.w, bias))));
            dt = softplusf(dt);
            S += dt;
            float du = dt * us[t*129 + d];
#pragma unroll
            for (int n = 0; n < NST; n++) {
                float a = __expf(dt * Ar[n]);
                h[n] = fmaf(a, h[n], du * xt[4 + n]);
            }
        }
#pragma unroll
        for (int n = 0; n < NST; n++) { o[n] = h[n]; o[16 + n] = __expf(S * Ar[n]); }
    }
}

// ---------------- scan pass 2: sequential chunk combine ----------------
__global__ void scan2_k(float* __restrict__ hp) {
    int idx = blockIdx.x * 256 + threadIdx.x;   // 8192 threads
    int dn = idx & 2047;
    int b = idx >> 11;
    int off = ((dn >> 4) << 5) + (dn & 15);
    long base = (long)b * NCH * (DIN*32) + off;
    float H = 0.f;
    for (int c = 0; c < NCH; c++) {
        float he = hp[base];
        float p  = hp[base + 16];
        hp[base] = H;
        H = fmaf(p, H, he);
        base += DIN*32;
    }
}

// ---------------- scan pass 3: replay + gate; out k-major [b][d][l] ----------------
__global__ __launch_bounds__(128) void scan3_k(const float* __restrict__ u,
                                               const float* __restrict__ xdbl,
                                               const float* __restrict__ xr,
                                               const float* __restrict__ Ap,
                                               const float* __restrict__ dtw,
                                               const float* __restrict__ dtb,
                                               const float* __restrict__ Dp,
                                               const float* __restrict__ hp,
                                               float* __restrict__ yg,
                                               const int* __restrict__ flagp) {
    __shared__ float xds[TCH*36];
    __shared__ float us[TCH*129];
    __shared__ float ys[TCH*129];
    int d = threadIdx.x;
    int c = blockIdx.x, b = blockIdx.y;
    long lc = (long)b*SEQL + c*TCH;
    for (int e = d; e < TCH*36; e += 128) xds[e] = xdbl[lc*36 + e];
    for (int e = d; e < TCH*DIN; e += 128) {
        int d2 = e >> 5, t = e & 31;
        us[t*129 + d2] = u[((long)b*DIN + d2)*SEQL + c*TCH + t];
    }
    float4 w = *(const float4*)&dtw[d*4];
    float bias = __ldg(&dtb[d]);
    float Dd = __ldg(&Dp[d]);
    int structured = *flagp;
    float A0 = Ap[d*NST];
    const float* hi = hp + (((long)b*NCH + c)*DIN + d)*32;
    __syncthreads();
    if (structured) {
        u64 h2[8];
#pragma unroll
        for (int p = 0; p < 8; p++) h2[p] = *(const u64*)&hi[2*p];
        for (int t = 0; t < TCH; t++) {
            const float* xt = xds + t*36;
            float dt = fmaf(xt[0], w.x, fmaf(xt[1], w.y, fmaf(xt[2], w.z, fmaf(xt[3], w.w, bias))));
            dt = softplusf(dt);
            float ut = us[t*129 + d];
            float du = dt * ut;
            float r = __expf(dt * A0);
            float r2 = r * r;
            u64 a2, rr2, du2, y2 = 0ULL;
            PKP(a2, r, r2); PK1(rr2, r2); PK1(du2, du);
#pragma unroll
            for (int p = 0; p < 8; p++) {
                u64 bp = *(const u64*)&xt[4 + 2*p];
                u64 cp = *(const u64*)&xt[20 + 2*p];
                u64 m;
                MUL2(m, du2, bp);
                FMA2(h2[p], a2, h2[p], m);
                FMA2(y2, h2[p], cp, y2);
                if (p < 7) MUL2(a2, a2, rr2);
            }
            float ylo, yhi;
            UNPK2(ylo, yhi, y2);
            float rt = xr[(lc + t)*256 + 128 + d];
            ys[t*129 + d] = fmaf(ut, Dd, ylo + yhi) * siluf(rt);
        }
    } else {
        float Ar[NST], h[NST];
#pragma unroll
        for (int n = 0; n < NST; n++) { Ar[n] = Ap[d*NST + n]; h[n] = hi[n]; }
        for (int t = 0; t < TCH; t++) {
            const float* xt = xds + t*36;
            float dt = fmaf(xt[0], w.x, fmaf(xt[1], w.y, fmaf(xt[2], w.z, fmaf(xt[3], w.w, bias))));
            dt = softplusf(dt);
            float ut = us[t*129 + d];
            float du = dt * ut;
            float y = 0.f;
#pragma unroll
            for (int n = 0; n < NST; n++) {
                float a = __expf(dt * Ar[n]);
                h[n] = fmaf(a, h[n], du * xt[4 + n]);
                y = fmaf(h[n], xt[20 + n], y);
            }
            float rt = xr[(lc + t)*256 + 128 + d];
            ys[t*129 + d] = fmaf(ut, Dd, y) * siluf(rt);
        }
    }
    __syncthreads();
    for (int e = d; e < TCH*DIN; e += 128) {
        int d2 = e >> 5, t = e & 31;
        yg[((long)b*DIN + d2)*SEQL + c*TCH + t] = ys[t*129 + d2];
    }
}

// ---------------- host ----------------
extern "C" void kernel_launch(void* const* d_in, const int* in_sizes, int n_in,
                              void* d_out, int out_size) {
    const float* x1 = (const float*)d_in[0];
    float* out = (float*)d_out;

    float *xr, *u, *xd, *hp, *yg, *xmid, *w1t, *wxt, *wot, *Ab;
    int* Afl;
    cudaGetSymbolAddress((void**)&xr,   g_xr);
    cudaGetSymbolAddress((void**)&u,    g_u);
    cudaGetSymbolAddress((void**)&xd,   g_xdbl);
    cudaGetSymbolAddress((void**)&hp,   g_hp);
    cudaGetSymbolAddress((void**)&yg,   g_yg);
    cudaGetSymbolAddress((void**)&xmid, g_xmid);
    cudaGetSymbolAddress((void**)&w1t,  g_w1t);
    cudaGetSymbolAddress((void**)&wxt,  g_wxt);
    cudaGetSymbolAddress((void**)&wot,  g_wot);
    cudaGetSymbolAddress((void**)&Ab,   g_Ab);
    cudaGetSymbolAddress((void**)&Afl,  g_Afl);

    cudaFuncSetAttribute(gemm_k, cudaFuncAttributeMaxDynamicSharedMemorySize, 128*192*4);

    for (int m = 0; m < 2; m++) {
        prep_k<<<136, 256>>>((const float*)d_in[1 + 9*m + 0], (const float*)d_in[1 + 9*m + 3],
                             (const float*)d_in[1 + 9*m + 8], (const float*)d_in[1 + 9*m + 6],
                             w1t + m*16384, wxt + m*8192, wot + m*8192, Ab + m*2048);
    }
    chkA_k<<<2, 256>>>(Ab, Ab + 2048, Afl);

    for (int m = 0; m < 2; m++) {
        const float* cw  = (const float*)d_in[1 + 9*m + 1];
        const float* cb  = (const float*)d_in[1 + 9*m + 2];
        const float* dtw = (const float*)d_in[1 + 9*m + 4];
        const float* dtb = (const float*)d_in[1 + 9*m + 5];
        const float* Dp  = (const float*)d_in[1 + 9*m + 7];
        const float* lng = (const float*)d_in[19 + 2*m];
        const float* lnb = (const float*)d_in[20 + 2*m];
        const float* Abm = Ab + m*2048;
        const int*   flm = Afl + m;

        const float* Xin = (m == 0) ? x1 : xmid;      // k-major [b][64][4096]
        float* gout = (m == 0) ? xmid : out;          // k-major [b][64][4096]

        // in_proj: K=64, N=256, row-major out xr
        gemm_k<<<dim3(SEQL/128, 4, BATCH), 256, 64*192*4>>>(
            Xin, w1t + m*16384, xr, 64, 256, 256, 0, nullptr, nullptr);
        // conv + silu -> u [b][128][4096]
        conv_silu_k<<<dim3(SEQL/32, BATCH), 256>>>(xr, cw, cb, u);
        // x_proj: K=128, N=64(36), row-major out xd
        gemm_k<<<dim3(SEQL/128, 1, BATCH), 256, 128*192*4>>>(
            u, wxt + m*8192, xd, 128, 64, 36, 1, nullptr, nullptr);
        // chunked selective scan
        scan1_k<<<dim3(NCH, BATCH), DIN>>>(u, xd, Abm, dtw, dtb, hp, flm);
        scan2_k<<<32, 256>>>(hp);
        scan3_k<<<dim3(NCH, BATCH), DIN>>>(u, xd, xr, Abm, dtw, dtb, Dp, hp, yg, flm);
        // out_proj + LayerNorm + transposed write
        gemm_k<<<dim3(SEQL/128, 1, BATCH), 256, 128*192*4>>>(
            yg, wot + m*8192, gout, 128, 64, 64, 2, lng, lnb);
    }
}

// round 5
// speedup vs baseline: 1.3998x; 1.0486x over previous
#include <cuda_runtime.h>

#define BATCH 4
#define SEQL  4096
#define DIN   128
#define NST   16
#define TCH   32
#define NCH   128   /* SEQL / TCH */

typedef unsigned long long u64;

#define FMA2(d, a, b, c) asm("fma.rn.f32x2 %0, %1, %2, %3;" : "=l"(d) : "l"(a), "l"(b), "l"(c))
#define MUL2(d, a, b)    asm("mul.rn.f32x2 %0, %1, %2;" : "=l"(d) : "l"(a), "l"(b))
#define UNPK2(x, y, in)  asm("mov.b64 {%0, %1}, %2;" : "=f"(x), "=f"(y) : "l"(in))
#define PK1(d, x)        asm("mov.b64 %0, {%1, %1};" : "=l"(d) : "f"(x))
#define PKP(d, x, y)     asm("mov.b64 %0, {%1, %2};" : "=l"(d) : "f"(x), "f"(y))

#define CPA16(dst, src)  asm volatile("cp.async.cg.shared.global [%0], [%1], 16;" :: "r"(dst), "l"(src) : "memory")
#define CPCOM()          asm volatile("cp.async.commit_group;" ::: "memory")
#define CPWAIT1()        asm volatile("cp.async.wait_group 1;" ::: "memory")
#define CPWAIT0()        asm volatile("cp.async.wait_group 0;" ::: "memory")

// ---------------- scratch (device globals; no allocation) ----------------
__device__ float g_xr  [BATCH*SEQL*256];   // in_proj output (u | res), row-major [l][256]
__device__ float g_u   [BATCH*DIN*SEQL];   // silu(conv(u)), k-major [b][d][l]
__device__ float g_xdbl[BATCH*SEQL*36];    // x_proj output, row-major [l][36] (dt4|B16|C16)
__device__ float g_hp  [BATCH*NCH*DIN*32]; // per-chunk [h_end(16)|P(16)] -> H_init
__device__ float g_yg  [BATCH*DIN*SEQL];   // gated scan output, k-major [b][d][l]
__device__ float g_xmid[BATCH*64*SEQL];    // between mambas, k-major [b][c][l]
__device__ float g_w1t [2][64*256];        // in_proj W transposed [k][n]
__device__ float g_wxt [2][128*64];        // x_proj W transposed, zero-padded to 64
__device__ float g_wot [2][128*64];        // out_proj W transposed
__device__ float g_Ab  [2][DIN*NST];       // A = -exp(Alog)
__device__ int   g_Afl [2];                // 1 if A[d][n] == (n+1)*A[d][0]
__device__ unsigned g_ctr = 0;             // grid-barrier ticket counter (monotonic)

__device__ __forceinline__ float softplusf(float x) {
    return x > 15.f ? x : __logf(1.f + __expf(x));
}
__device__ __forceinline__ float siluf(float x) {
    return x / (1.f + __expf(-x));
}

// ---------------- prep: both mambas in one launch ----------------
__global__ void prep_k(const float* __restrict__ iw0, const float* __restrict__ xp0,
                       const float* __restrict__ ow0, const float* __restrict__ al0,
                       const float* __restrict__ iw1, const float* __restrict__ xp1,
                       const float* __restrict__ ow1, const float* __restrict__ al1,
                       float* __restrict__ w1t, float* __restrict__ wxt,
                       float* __restrict__ wot, float* __restrict__ Ab) {
    int m = blockIdx.y;
    const float* in_w  = m ? iw1 : iw0;
    const float* xproj = m ? xp1 : xp0;
    const float* out_w = m ? ow1 : ow0;
    const float* Alog  = m ? al1 : al0;
    float* w1 = w1t + m*16384;
    float* wx = wxt + m*8192;
    float* wo = wot + m*8192;
    float* Am = Ab  + m*2048;
    int idx = blockIdx.x * 256 + threadIdx.x;
    if (idx < 16384) { int k = idx >> 8, n = idx & 255; w1[idx] = in_w[n*64 + k]; return; }
    idx -= 16384;
    if (idx < 8192)  { int k = idx >> 6, n = idx & 63; wx[idx] = (n < 36) ? xproj[n*128 + k] : 0.f; return; }
    idx -= 8192;
    if (idx < 8192)  { int k = idx >> 6, n = idx & 63; wo[idx] = out_w[n*128 + k]; return; }
    idx -= 8192;
    if (idx < 2048)  Am[idx] = -expf(Alog[idx]);
}

__global__ void chkA_k(const float* __restrict__ A0, const float* __restrict__ A1,
                       int* __restrict__ fl) {
    const float* A = blockIdx.x ? A1 : A0;
    __shared__ int ok;
    if (threadIdx.x == 0) ok = 1;
    __syncthreads();
    int bad = 0;
    for (int e = threadIdx.x; e < DIN*NST; e += 256) {
        int d = e >> 4, n = e & 15;
        float expv = (float)(n + 1) * A[d*16];
        if (fabsf(A[e] - expv) > 1e-5f * fabsf(expv) + 1e-20f) bad = 1;
    }
    if (bad) atomicAnd(&ok, 0);
    __syncthreads();
    if (threadIdx.x == 0) fl[blockIdx.x] = ok;
}

// ---------------- pipelined GEMM: X k-major [b][K][4096]; tile 64L x 64N ----------------
// 2-stage cp.async over k-tiles of 32. 4L x 4N per thread (2 f32x2 row-pairs).
// epi: 0 = row-major [l][Nout] at col n0; 1 = cols<36 to [l][36];
//      2 = LayerNorm over 64 cols + transposed write [b][64][4096].
__global__ __launch_bounds__(256) void gemm_k(
    const float* __restrict__ X, const float* __restrict__ Wt, float* __restrict__ Out,
    int K, int Nld, int Nout, int epi,
    const float* __restrict__ lng, const float* __restrict__ lnb)
{
    extern __shared__ float sm[];  // [2][32*64] X | [2][32*64] W  (then LN staging reuse)
    int tid = threadIdx.x;
    int l0 = blockIdx.x << 6;
    int n0 = blockIdx.y << 6;
    int b  = blockIdx.z;
    const float* Xb = X + (long)b * K * SEQL;
    int lj = tid >> 4, ng = tid & 15;
    int lb = lj << 2;
    unsigned smb = (unsigned)__cvta_generic_to_shared(sm);
    int ntiles = K >> 5;

    // issue tile 0 into stage 0
    {
#pragma unroll
        for (int i = 0; i < 2; i++) {
            int e = tid + (i << 8);
            int k = e >> 4, lq = e & 15;
            CPA16(smb + (((k << 6) + (lq << 2)) << 2),
                  Xb + (long)k * SEQL + l0 + (lq << 2));
        }
#pragma unroll
        for (int i = 0; i < 2; i++) {
            int e = tid + (i << 8);
            int k = e >> 4, nq = e & 15;
            CPA16(smb + 16384u + (((k << 6) + (nq << 2)) << 2),
                  Wt + (long)k * Nld + n0 + (nq << 2));
        }
        CPCOM();
    }

    u64 acc[2][4];
#pragma unroll
    for (int p = 0; p < 2; p++)
#pragma unroll
        for (int c = 0; c < 4; c++) acc[p][c] = 0ULL;

    for (int tt = 0; tt < ntiles; tt++) {
        int s = tt & 1;
        if (tt + 1 < ntiles) {
            int kofs = (tt + 1) << 5;
            int s2 = s ^ 1;
#pragma unroll
            for (int i = 0; i < 2; i++) {
                int e = tid + (i << 8);
                int k = e >> 4, lq = e & 15;
                CPA16(smb + (((s2 << 11) + (k << 6) + (lq << 2)) << 2),
                      Xb + (long)(kofs + k) * SEQL + l0 + (lq << 2));
            }
#pragma unroll
            for (int i = 0; i < 2; i++) {
                int e = tid + (i << 8);
                int k = e >> 4, nq = e & 15;
                CPA16(smb + 16384u + (((s2 << 11) + (k << 6) + (nq << 2)) << 2),
                      Wt + (long)(kofs + k) * Nld + n0 + (nq << 2));
            }
            CPCOM();
            CPWAIT1();
        } else {
            CPWAIT0();
        }
        __syncthreads();
        const float* xs = sm + (s << 11);
        const float* ws = sm + 4096 + (s << 11);
#pragma unroll 8
        for (int kk = 0; kk < 32; kk++) {
            ulonglong2 av = *(const ulonglong2*)&xs[(kk << 6) + lb];   // rows (0,1),(2,3)
            float4 wv = *(const float4*)&ws[(kk << 6) + (ng << 2)];
            u64 b0, b1, b2, b3;
            PK1(b0, wv.x); PK1(b1, wv.y); PK1(b2, wv.z); PK1(b3, wv.w);
            FMA2(acc[0][0], av.x, b0, acc[0][0]); FMA2(acc[0][1], av.x, b1, acc[0][1]);
            FMA2(acc[0][2], av.x, b2, acc[0][2]); FMA2(acc[0][3], av.x, b3, acc[0][3]);
            FMA2(acc[1][0], av.y, b0, acc[1][0]); FMA2(acc[1][1], av.y, b1, acc[1][1]);
            FMA2(acc[1][2], av.y, b2, acc[1][2]); FMA2(acc[1][3], av.y, b3, acc[1][3]);
        }
        __syncthreads();
    }

    if (epi == 0) {
#pragma unroll
        for (int p = 0; p < 2; p++) {
            float lo[4], hi[4];
#pragma unroll
            for (int c = 0; c < 4; c++) UNPK2(lo[c], hi[c], acc[p][c]);
            long r0 = ((long)b*SEQL + l0 + lb + 2*p) * Nout + n0 + (ng << 2);
            *(float4*)&Out[r0]        = make_float4(lo[0], lo[1], lo[2], lo[3]);
            *(float4*)&Out[r0 + Nout] = make_float4(hi[0], hi[1], hi[2], hi[3]);
        }
    } else if (epi == 1) {
        if (ng < 9) {
#pragma unroll
            for (int p = 0; p < 2; p++) {
                float lo[4], hi[4];
#pragma unroll
                for (int c = 0; c < 4; c++) UNPK2(lo[c], hi[c], acc[p][c]);
                long r0 = ((long)b*SEQL + l0 + lb + 2*p) * 36 + (ng << 2);
                *(float4*)&Out[r0]      = make_float4(lo[0], lo[1], lo[2], lo[3]);
                *(float4*)&Out[r0 + 36] = make_float4(hi[0], hi[1], hi[2], hi[3]);
            }
        }
    } else {
        // LayerNorm over 64 cols + transposed coalesced write (n0==0)
        float* st  = sm;          // [64][65]
        float* st2 = sm + 4160;   // [64][65] transposed
#pragma unroll
        for (int p = 0; p < 2; p++) {
#pragma unroll
            for (int c = 0; c < 4; c++) {
                float lo, hi;
                UNPK2(lo, hi, acc[p][c]);
                st[(lb + 2*p)*65 + (ng << 2) + c]     = lo;
                st[(lb + 2*p + 1)*65 + (ng << 2) + c] = hi;
            }
        }
        __syncthreads();
        int row = tid >> 2, q = tid & 3;
        float v[16], s = 0.f, s2 = 0.f;
#pragma unroll
        for (int j = 0; j < 16; j++) {
            float x = st[row*65 + q*16 + j];
            v[j] = x; s += x; s2 += x * x;
        }
        s  += __shfl_xor_sync(0xffffffffu, s, 1);
        s2 += __shfl_xor_sync(0xffffffffu, s2, 1);
        s  += __shfl_xor_sync(0xffffffffu, s, 2);
        s2 += __shfl_xor_sync(0xffffffffu, s2, 2);
        float mean = s * 0.015625f;
        float var  = s2 * 0.015625f - mean * mean;
        float rstd = rsqrtf(var + 1e-5f);
#pragma unroll
        for (int j = 0; j < 16; j++) {
            int n = q*16 + j;
            st2[n*65 + row] = (v[j] - mean) * rstd * __ldg(&lng[n]) + __ldg(&lnb[n]);
        }
        __syncthreads();
        int n2 = tid >> 2, lq = tid & 3;
#pragma unroll
        for (int i = 0; i < 4; i++) {
            int l = (lq << 4) + (i << 2);
            float4 o4 = make_float4(st2[n2*65 + l], st2[n2*65 + l + 1],
                                    st2[n2*65 + l + 2], st2[n2*65 + l + 3]);
            *(float4*)&Out[((long)b*64 + n2)*SEQL + l0 + l] = o4;
        }
    }
}

// ---------------- causal depthwise conv (k=4) + silu; out k-major [b][d][l] ----------------
__global__ __launch_bounds__(256) void conv_silu_k(const float* __restrict__ xr,
                                                   const float* __restrict__ cw,
                                                   const float* __restrict__ cb,
                                                   float* __restrict__ u) {
    __shared__ float sx[35*132];
    __shared__ float su[32*129];
    int tid = threadIdx.x;
    int l0 = blockIdx.x << 5;
    int b  = blockIdx.y;
    for (int e = tid; e < 35*128; e += 256) {
        int row = e >> 7, dd = e & 127;
        int lg = l0 - 3 + row;
        sx[row*132 + dd] = (lg >= 0) ? xr[((long)b*SEQL + lg)*256 + dd] : 0.f;
    }
    __syncthreads();
    int d = tid >> 1, half = tid & 1;
    float4 w = *(const float4*)&cw[d*4];
    float bias = __ldg(&cb[d]);
#pragma unroll
    for (int j = 0; j < 16; j++) {
        int l = half*16 + j;
        float s = bias + w.w*sx[(l+3)*132 + d] + w.z*sx[(l+2)*132 + d]
                       + w.y*sx[(l+1)*132 + d] + w.x*sx[l*132 + d];
        su[l*129 + d] = siluf(s);
    }
    __syncthreads();
    for (int e = tid; e < 4096; e += 256) {
        int d2 = e >> 5, li = e & 31;
        u[((long)b*DIN + d2)*SEQL + l0 + li] = su[li*129 + d2];
    }
}

// ---------------- grid barrier (all 512 blocks resident by construction) ----------------
__device__ __forceinline__ void gridbar(int tid) {
    __syncthreads();
    if (tid == 0) {
        __threadfence();
        unsigned t = atomicAdd(&g_ctr, 1u);
        unsigned target = (t & ~511u) + 512u;
        volatile unsigned* p = &g_ctr;
        while ((int)(*p - target) < 0) __nanosleep(64);
    }
    __syncthreads();
    __threadfence();
}

// ---------------- fused selective scan: pass1 + combine + pass3 in one kernel ----------------
// grid MUST be (NCH, BATCH) = 512 blocks of 128 threads; smem 54KB -> 4 blocks/SM, all resident.
__global__ __launch_bounds__(128) void scanf_k(const float* __restrict__ u,
                                               const float* __restrict__ xdbl,
                                               const float* __restrict__ xr,
                                               const float* __restrict__ Ap,
                                               const float* __restrict__ dtw,
                                               const float* __restrict__ dtb,
                                               const float* __restrict__ Dp,
                                               float* __restrict__ hp,
                                               float* __restrict__ yg,
                                               const int* __restrict__ flagp) {
    __shared__ float xds[TCH*36];
    __shared__ float us[TCH*129];
    __shared__ float dts[TCH*128];
    __shared__ float ys[TCH*129];
    int d = threadIdx.x;
    int c = blockIdx.x, b = blockIdx.y;
    long lc = (long)b*SEQL + c*TCH;
    for (int e = d; e < TCH*36; e += 128) xds[e] = xdbl[lc*36 + e];
    for (int e = d; e < TCH*DIN; e += 128) {
        int d2 = e >> 5, t = e & 31;
        us[t*129 + d2] = u[((long)b*DIN + d2)*SEQL + c*TCH + t];
    }
    float4 w = *(const float4*)&dtw[d*4];
    float bias = __ldg(&dtb[d]);
    float Dd = __ldg(&Dp[d]);
    int structured = *flagp;
    float A0 = Ap[d*NST];
    float* o = hp + (((long)b*NCH + c)*DIN + d)*32;
    __syncthreads();

    // ---- pass 1: local scan from h=0; also cache softplus(dt) in smem ----
    float S = 0.f;
    if (structured) {
        u64 h2[8];
#pragma unroll
        for (int p = 0; p < 8; p++) h2[p] = 0ULL;
        for (int t = 0; t < TCH; t++) {
            const float* xt = xds + t*36;
            float dt = fmaf(xt[0], w.x, fmaf(xt[1], w.y, fmaf(xt[2], w.z, fmaf(xt[3], w.w, bias))));
            dt = softplusf(dt);
            dts[t*128 + d] = dt;
            S += dt;
            float du = dt * us[t*129 + d];
            float r = __expf(dt * A0);
            float r2 = r * r;
            u64 a2, rr2, du2;
            PKP(a2, r, r2); PK1(rr2, r2); PK1(du2, du);
#pragma unroll
            for (int p = 0; p < 8; p++) {
                u64 bp = *(const u64*)&xt[4 + 2*p];
                u64 m;
                MUL2(m, du2, bp);
                FMA2(h2[p], a2, h2[p], m);
                if (p < 7) MUL2(a2, a2, rr2);
            }
        }
#pragma unroll
        for (int p = 0; p < 8; p++) *(u64*)&o[2*p] = h2[p];
        float q = __expf(S * A0), qc = q;
#pragma unroll
        for (int n = 0; n < NST; n++) { o[16 + n] = qc; qc *= q; }
    } else {
        float Ar[NST], h[NST];
#pragma unroll
        for (int n = 0; n < NST; n++) { Ar[n] = Ap[d*NST + n]; h[n] = 0.f; }
        for (int t = 0; t < TCH; t++) {
            const float* xt = xds + t*36;
            float dt = fmaf(xt[0], w.x, fmaf(xt[1], w.y, fmaf(xt[2], w.z, fmaf(xt[3], w.w, bias))));
            dt = softplusf(dt);
            dts[t*128 + d] = dt;
            S += dt;
            float du = dt * us[t*129 + d];
#pragma unroll
            for (int n = 0; n < NST; n++) {
                float a = __expf(dt * Ar[n]);
                h[n] = fmaf(a, h[n], du * xt[4 + n]);
            }
        }
#pragma unroll
        for (int n = 0; n < NST; n++) { o[n] = h[n]; o[16 + n] = __expf(S * Ar[n]); }
    }

    gridbar(d);

    // ---- pass 2: sequential chunk combine on 64 blocks (8192 threads) ----
    int bid = b*NCH + c;
    if (bid < 64) {
        int widx = bid*128 + d;                 // 0..8191
        int b2 = widx >> 11;
        int dn = widx & 2047;
        int off = ((dn >> 4) << 5) + (dn & 15);
        long base = (long)b2 * NCH * (DIN*32) + off;
        float H = 0.f;
        for (int cc = 0; cc < NCH; cc++) {
            float he = hp[base];
            float p  = hp[base + 16];
            hp[base] = H;
            H = fmaf(p, H, he);
            base += DIN*32;
        }
    }

    gridbar(d);

    // ---- pass 3: replay from H_init; y = C.h + u*D; gate by silu(res) ----
    const float* hi = o;
    if (structured) {
        u64 h2[8];
#pragma unroll
        for (int p = 0; p < 8; p++) h2[p] = *(const u64*)&hi[2*p];
        for (int t = 0; t < TCH; t++) {
            const float* xt = xds + t*36;
            float dt = dts[t*128 + d];
            float ut = us[t*129 + d];
            float du = dt * ut;
            float r = __expf(dt * A0);
            float r2 = r * r;
            u64 a2, rr2, du2, y2 = 0ULL;
            PKP(a2, r, r2); PK1(rr2, r2); PK1(du2, du);
#pragma unroll
            for (int p = 0; p < 8; p++) {
                u64 bp = *(const u64*)&xt[4 + 2*p];
                u64 cp = *(const u64*)&xt[20 + 2*p];
                u64 m;
                MUL2(m, du2, bp);
                FMA2(h2[p], a2, h2[p], m);
                FMA2(y2, h2[p], cp, y2);
                if (p < 7) MUL2(a2, a2, rr2);
            }
            float ylo, yhi;
            UNPK2(ylo, yhi, y2);
            float rt = xr[(lc + t)*256 + 128 + d];
            ys[t*129 + d] = fmaf(ut, Dd, ylo + yhi) * siluf(rt);
        }
    } else {
        float Ar[NST], h[NST];
#pragma unroll
        for (int n = 0; n < NST; n++) { Ar[n] = Ap[d*NST + n]; h[n] = hi[n]; }
        for (int t = 0; t < TCH; t++) {
            const float* xt = xds + t*36;
            float dt = dts[t*128 + d];
            float ut = us[t*129 + d];
            float du = dt * ut;
            float y = 0.f;
#pragma unroll
            for (int n = 0; n < NST; n++) {
                float a = __expf(dt * Ar[n]);
                h[n] = fmaf(a, h[n], du * xt[4 + n]);
                y = fmaf(h[n], xt[20 + n], y);
            }
            float rt = xr[(lc + t)*256 + 128 + d];
            ys[t*129 + d] = fmaf(ut, Dd, y) * siluf(rt);
        }
    }
    __syncthreads();
    for (int e = d; e < TCH*DIN; e += 128) {
        int d2 = e >> 5, t = e & 31;
        yg[((long)b*DIN + d2)*SEQL + c*TCH + t] = ys[t*129 + d2];
    }
}

// ---------------- host ----------------
extern "C" void kernel_launch(void* const* d_in, const int* in_sizes, int n_in,
                              void* d_out, int out_size) {
    const float* x1 = (const float*)d_in[0];
    float* out = (float*)d_out;

    float *xr, *u, *xd, *hp, *yg, *xmid, *w1t, *wxt, *wot, *Ab;
    int* Afl;
    cudaGetSymbolAddress((void**)&xr,   g_xr);
    cudaGetSymbolAddress((void**)&u,    g_u);
    cudaGetSymbolAddress((void**)&xd,   g_xdbl);
    cudaGetSymbolAddress((void**)&hp,   g_hp);
    cudaGetSymbolAddress((void**)&yg,   g_yg);
    cudaGetSymbolAddress((void**)&xmid, g_xmid);
    cudaGetSymbolAddress((void**)&w1t,  g_w1t);
    cudaGetSymbolAddress((void**)&wxt,  g_wxt);
    cudaGetSymbolAddress((void**)&wot,  g_wot);
    cudaGetSymbolAddress((void**)&Ab,   g_Ab);
    cudaGetSymbolAddress((void**)&Afl,  g_Afl);

    prep_k<<<dim3(136, 2), 256>>>(
        (const float*)d_in[1], (const float*)d_in[4], (const float*)d_in[9], (const float*)d_in[7],
        (const float*)d_in[10], (const float*)d_in[13], (const float*)d_in[18], (const float*)d_in[16],
        w1t, wxt, wot, Ab);
    chkA_k<<<2, 256>>>(Ab, Ab + 2048, Afl);

    const int GSM = 33280;  // gemm dynamic smem (pipeline 32KB; LN staging 32.5KB)

    for (int m = 0; m < 2; m++) {
        const float* cw  = (const float*)d_in[1 + 9*m + 1];
        const float* cb  = (const float*)d_in[1 + 9*m + 2];
        const float* dtw = (const float*)d_in[1 + 9*m + 4];
        const float* dtb = (const float*)d_in[1 + 9*m + 5];
        const float* Dp  = (const float*)d_in[1 + 9*m + 7];
        const float* lng = (const float*)d_in[19 + 2*m];
        const float* lnb = (const float*)d_in[20 + 2*m];
        const float* Abm = Ab + m*2048;
        const int*   flm = Afl + m;

        const float* Xin = (m == 0) ? x1 : xmid;      // k-major [b][64][4096]
        float* gout = (m == 0) ? xmid : out;          // k-major [b][64][4096]

        // in_proj: K=64, N=256 -> xr row-major
        gemm_k<<<dim3(SEQL/64, 4, BATCH), 256, GSM>>>(
            Xin, w1t + m*16384, xr, 64, 256, 256, 0, nullptr, nullptr);
        // conv + silu -> u [b][128][4096]
        conv_silu_k<<<dim3(SEQL/32, BATCH), 256>>>(xr, cw, cb, u);
        // x_proj: K=128, N=64(36) -> xd row-major
        gemm_k<<<dim3(SEQL/64, 1, BATCH), 256, GSM>>>(
            u, wxt + m*8192, xd, 128, 64, 36, 1, nullptr, nullptr);
        // fused chunked selective scan (pass1 + combine + pass3)
        scanf_k<<<dim3(NCH, BATCH), DIN>>>(u, xd, xr, Abm, dtw, dtb, Dp, hp, yg, flm);
        // out_proj + LayerNorm + transposed write
        gemm_k<<<dim3(SEQL/64, 1, BATCH), 256, GSM>>>(
            yg, wot + m*8192, gout, 128, 64, 64, 2, lng, lnb);
    }
}